// round 1
// baseline (speedup 1.0000x reference)
#include <cuda_runtime.h>
#include <math.h>

#define Bn 4
#define Tn 2048
#define En 1024
#define Hn 16
#define HSn 64
#define Mn (Bn * Tn)   // 8192

// Scratch buffers (device globals: allocation-free rule)
__device__ float g_k[Mn * En];
__device__ float g_q[Mn * En];
__device__ float g_v[Mn * En];
__device__ float g_att[Mn * En];

// ---------------------------------------------------------------------------
// NT GEMM: C[M,N] = A[M,K] @ Bm[N,K]^T (+ bias[n])
// 64x64 tile, BK=16, 256 threads, 4x4 microtile per thread.
// ---------------------------------------------------------------------------
template <bool BIAS>
__global__ void __launch_bounds__(256)
gemm_nt_kernel(const float* __restrict__ A, const float* __restrict__ Bm,
               const float* __restrict__ bias, float* __restrict__ C,
               int Mdim, int Ndim, int Kdim) {
    __shared__ float As[16][65];
    __shared__ float Bs[16][65];
    const int tid = threadIdx.x;
    const int tx = tid & 15;
    const int ty = tid >> 4;
    const int m0 = blockIdx.x * 64;
    const int n0 = blockIdx.y * 64;

    float acc[4][4];
#pragma unroll
    for (int i = 0; i < 4; i++)
#pragma unroll
        for (int j = 0; j < 4; j++) acc[i][j] = 0.f;

    for (int k0 = 0; k0 < Kdim; k0 += 16) {
#pragma unroll
        for (int i = 0; i < 4; i++) {
            int idx = tid + i * 256;          // 0..1023
            int r = idx >> 4;                 // 0..63
            int c = idx & 15;                 // 0..15
            As[c][r] = A[(size_t)(m0 + r) * Kdim + k0 + c];
            Bs[c][r] = Bm[(size_t)(n0 + r) * Kdim + k0 + c];
        }
        __syncthreads();
#pragma unroll
        for (int kk = 0; kk < 16; kk++) {
            float a[4], b[4];
#pragma unroll
            for (int i = 0; i < 4; i++) a[i] = As[kk][ty * 4 + i];
#pragma unroll
            for (int j = 0; j < 4; j++) b[j] = Bs[kk][tx * 4 + j];
#pragma unroll
            for (int i = 0; i < 4; i++)
#pragma unroll
                for (int j = 0; j < 4; j++)
                    acc[i][j] = fmaf(a[i], b[j], acc[i][j]);
        }
        __syncthreads();
    }

#pragma unroll
    for (int i = 0; i < 4; i++) {
        int m = m0 + ty * 4 + i;
#pragma unroll
        for (int j = 0; j < 4; j++) {
            int n = n0 + tx * 4 + j;
            float v = acc[i][j];
            if (BIAS) v += bias[n];
            C[(size_t)m * Ndim + n] = v;
        }
    }
}

// ---------------------------------------------------------------------------
// Flash attention (roles swapped: "query" = k-proj, "key" = q-proj).
// One block = (64 t-rows, one head, one batch). 256 threads, 4x4 microtiles.
// smem: Qt[64][64], Kt[64][65], Vt[64][64], Ps[64][65] = 66048 B dynamic.
// ---------------------------------------------------------------------------
__global__ void __launch_bounds__(256)
attn_kernel(const float* __restrict__ Kp, const float* __restrict__ Qp,
            const float* __restrict__ Vp, float* __restrict__ Out) {
    extern __shared__ float sm[];
    float* Qt = sm;                    // [64][64]
    float* Kt = Qt + 64 * 64;          // [64][65]
    float* Vt = Kt + 64 * 65;          // [64][64]
    float* Ps = Vt + 64 * 64;          // [64][65]

    const int tid = threadIdx.x;
    const int tx = tid & 15;
    const int ty = tid >> 4;
    const int tb = blockIdx.x;
    const int h = blockIdx.y;
    const int b = blockIdx.z;
    const float scale = 0.125f;        // HS^-0.5

    const float* kbase = Kp + (size_t)b * Tn * En + h * HSn;
    const float* qbase = Qp + (size_t)b * Tn * En + h * HSn;
    const float* vbase = Vp + (size_t)b * Tn * En + h * HSn;

    const int t0 = tb * 64;

    // Load Q tile (k-projection rows t0..t0+63)
#pragma unroll
    for (int i = 0; i < 16; i++) {
        int idx = tid + i * 256;
        int r = idx >> 6, c = idx & 63;
        Qt[r * 64 + c] = kbase[(size_t)(t0 + r) * En + c];
    }

    float m_i[4], l_i[4], o[4][4];
#pragma unroll
    for (int i = 0; i < 4; i++) {
        m_i[i] = -INFINITY;
        l_i[i] = 0.f;
#pragma unroll
        for (int j = 0; j < 4; j++) o[i][j] = 0.f;
    }

    for (int sb = 0; sb <= tb; sb++) {
        const int s0 = sb * 64;
        __syncthreads();   // prior-iter reads of Kt/Vt done; also fences Qt load
#pragma unroll
        for (int i = 0; i < 16; i++) {
            int idx = tid + i * 256;
            int r = idx >> 6, c = idx & 63;
            Kt[r * 65 + c] = qbase[(size_t)(s0 + r) * En + c];
            Vt[r * 64 + c] = vbase[(size_t)(s0 + r) * En + c];
        }
        __syncthreads();

        // S = Qt @ Kt^T
        float s[4][4];
#pragma unroll
        for (int i = 0; i < 4; i++)
#pragma unroll
            for (int j = 0; j < 4; j++) s[i][j] = 0.f;
        for (int d = 0; d < 64; d++) {
            float a[4], bl[4];
#pragma unroll
            for (int i = 0; i < 4; i++) a[i] = Qt[(ty * 4 + i) * 64 + d];
#pragma unroll
            for (int j = 0; j < 4; j++) bl[j] = Kt[(tx * 4 + j) * 65 + d];
#pragma unroll
            for (int i = 0; i < 4; i++)
#pragma unroll
                for (int j = 0; j < 4; j++)
                    s[i][j] = fmaf(a[i], bl[j], s[i][j]);
        }

        const bool diag = (sb == tb);
#pragma unroll
        for (int i = 0; i < 4; i++) {
            int t = t0 + ty * 4 + i;
#pragma unroll
            for (int j = 0; j < 4; j++) {
                int ss = s0 + tx * 4 + j;
                s[i][j] *= scale;
                if (diag && ss > t) s[i][j] = -INFINITY;
            }
        }

        // online softmax per row (row shared by the 16 tx-threads of one ty)
#pragma unroll
        for (int i = 0; i < 4; i++) {
            float rm = fmaxf(fmaxf(s[i][0], s[i][1]), fmaxf(s[i][2], s[i][3]));
#pragma unroll
            for (int msk = 8; msk >= 1; msk >>= 1)
                rm = fmaxf(rm, __shfl_xor_sync(0xffffffffu, rm, msk));
            float mn = fmaxf(m_i[i], rm);
            float corr = __expf(m_i[i] - mn);   // 0 on first block (m_i = -inf)
            float rs = 0.f;
#pragma unroll
            for (int j = 0; j < 4; j++) {
                float p = __expf(s[i][j] - mn);
                s[i][j] = p;
                rs += p;
            }
#pragma unroll
            for (int msk = 8; msk >= 1; msk >>= 1)
                rs += __shfl_xor_sync(0xffffffffu, rs, msk);
            l_i[i] = l_i[i] * corr + rs;
            m_i[i] = mn;
#pragma unroll
            for (int j = 0; j < 4; j++) o[i][j] *= corr;
        }

        // stage P to smem (redistribute s-dim -> d-dim ownership)
#pragma unroll
        for (int i = 0; i < 4; i++)
#pragma unroll
            for (int j = 0; j < 4; j++)
                Ps[(ty * 4 + i) * 65 + tx * 4 + j] = s[i][j];
        __syncthreads();

        // O += P @ V
        for (int ss = 0; ss < 64; ss++) {
            float a[4], bl[4];
#pragma unroll
            for (int i = 0; i < 4; i++) a[i] = Ps[(ty * 4 + i) * 65 + ss];
#pragma unroll
            for (int j = 0; j < 4; j++) bl[j] = Vt[ss * 64 + tx * 4 + j];
#pragma unroll
            for (int i = 0; i < 4; i++)
#pragma unroll
                for (int j = 0; j < 4; j++)
                    o[i][j] = fmaf(a[i], bl[j], o[i][j]);
        }
    }

    float* obase = Out + (size_t)b * Tn * En + h * HSn;
#pragma unroll
    for (int i = 0; i < 4; i++) {
        float inv = 1.f / l_i[i];
#pragma unroll
        for (int j = 0; j < 4; j++)
            obase[(size_t)(t0 + ty * 4 + i) * En + tx * 4 + j] = o[i][j] * inv;
    }
}

// ---------------------------------------------------------------------------

static const int ATTN_SMEM = (64 * 64 + 64 * 65 + 64 * 64 + 64 * 65) * 4;  // 66048

extern "C" void kernel_launch(void* const* d_in, const int* in_sizes, int n_in,
                              void* d_out, int out_size) {
    (void)in_sizes; (void)n_in; (void)out_size;
    const float* x  = (const float*)d_in[0];
    const float* Wk = (const float*)d_in[1];
    const float* Wq = (const float*)d_in[2];
    const float* Wv = (const float*)d_in[3];
    const float* Wo = (const float*)d_in[4];
    const float* bo = (const float*)d_in[5];
    float* out = (float*)d_out;

    float *gk, *gq, *gv, *ga;
    cudaGetSymbolAddress((void**)&gk, g_k);
    cudaGetSymbolAddress((void**)&gq, g_q);
    cudaGetSymbolAddress((void**)&gv, g_v);
    cudaGetSymbolAddress((void**)&ga, g_att);

    cudaFuncSetAttribute(attn_kernel,
                         cudaFuncAttributeMaxDynamicSharedMemorySize, ATTN_SMEM);

    dim3 gproj(Mn / 64, En / 64);
    gemm_nt_kernel<false><<<gproj, 256>>>(x, Wk, nullptr, gk, Mn, En, En);
    gemm_nt_kernel<false><<<gproj, 256>>>(x, Wq, nullptr, gq, Mn, En, En);
    gemm_nt_kernel<false><<<gproj, 256>>>(x, Wv, nullptr, gv, Mn, En, En);

    dim3 gattn(Tn / 64, Hn, Bn);
    attn_kernel<<<gattn, 256, ATTN_SMEM>>>(gk, gq, gv, ga);

    gemm_nt_kernel<true><<<gproj, 256>>>(ga, Wo, bo, out, Mn, En, En);
}

// round 2
// speedup vs baseline: 2.3804x; 2.3804x over previous
#include <cuda_runtime.h>
#include <math.h>

#define Bn 4
#define Tn 2048
#define En 1024
#define Hn 16
#define HSn 64
#define Mn (Bn * Tn)   // 8192

// Scratch buffers (device globals: allocation-free rule)
__device__ float g_k[Mn * En];
__device__ float g_q[Mn * En];
__device__ float g_v[Mn * En];
__device__ float g_att[Mn * En];

// ---------------------------------------------------------------------------
// TF32 tensor-core NT GEMM: C[M,N] = A[M,K] @ Bm[N,K]^T (+ bias[n])
// 128x128 block tile, BK=32, 256 threads, 8 warps of 64x32,
// mma.sync.aligned.m16n8k8.row.col.f32.tf32.tf32.f32.
// Smem XOR-swizzled in 16B groups: phys_group = k_group ^ (row & 7)
// -> conflict-free 128-bit stores and conflict-free fragment loads.
// ---------------------------------------------------------------------------
__device__ __forceinline__ unsigned f2tf32(float f) {
    unsigned r;
    asm("cvt.rna.tf32.f32 %0, %1;" : "=r"(r) : "f"(f));
    return r;
}

template <bool BIAS>
__global__ void __launch_bounds__(256, 2)
gemm_tc(const float* __restrict__ A, const float* __restrict__ Bm,
        const float* __restrict__ bias, float* __restrict__ C,
        int Kdim, int Ndim) {
    __shared__ unsigned As[128 * 32];
    __shared__ unsigned Bs[128 * 32];

    const int tid  = threadIdx.x;
    const int lane = tid & 31;
    const int warp = tid >> 5;
    const int wm   = warp >> 2;      // 0..1 -> m offset wm*64
    const int wn   = warp & 3;       // 0..3 -> n offset wn*32
    const int m0   = blockIdx.x * 128;
    const int n0   = blockIdx.y * 128;

    float acc[4][4][4];
#pragma unroll
    for (int mi = 0; mi < 4; mi++)
#pragma unroll
        for (int ni = 0; ni < 4; ni++)
#pragma unroll
            for (int r = 0; r < 4; r++) acc[mi][ni][r] = 0.f;

    const int lr = lane >> 2;        // 0..7
    const int lc = lane & 3;         // 0..3

    for (int k0 = 0; k0 < Kdim; k0 += 32) {
        // ---- global -> smem (tf32 round-to-nearest at store time) ----
#pragma unroll
        for (int i = 0; i < 4; i++) {
            int f   = tid + i * 256;         // 0..1023
            int row = f >> 3;                // 0..127
            int c4  = f & 7;                 // 16B group within BK=32
            int sg  = ((c4 ^ (row & 7)) << 2);
            float4 av = *(const float4*)(A  + (size_t)(m0 + row) * Kdim + k0 + c4 * 4);
            float4 bv = *(const float4*)(Bm + (size_t)(n0 + row) * Kdim + k0 + c4 * 4);
            uint4 at = make_uint4(f2tf32(av.x), f2tf32(av.y), f2tf32(av.z), f2tf32(av.w));
            uint4 bt = make_uint4(f2tf32(bv.x), f2tf32(bv.y), f2tf32(bv.z), f2tf32(bv.w));
            *(uint4*)(&As[row * 32 + sg]) = at;
            *(uint4*)(&Bs[row * 32 + sg]) = bt;
        }
        __syncthreads();

        // ---- 4 k-steps of k=8 ----
#pragma unroll
        for (int kk = 0; kk < 4; kk++) {
            unsigned a[4][4], b[4][2];
#pragma unroll
            for (int mi = 0; mi < 4; mi++) {
                int r  = wm * 64 + mi * 16 + lr;     // row & 7 == lr & 7 (base mult of 16)
                int g0 = (((2 * kk)     ^ (r & 7)) << 2);
                int g1 = (((2 * kk + 1) ^ (r & 7)) << 2);
                a[mi][0] = As[r * 32 + g0 + lc];
                a[mi][1] = As[(r + 8) * 32 + g0 + lc];   // (r+8)&7 == r&7
                a[mi][2] = As[r * 32 + g1 + lc];
                a[mi][3] = As[(r + 8) * 32 + g1 + lc];
            }
#pragma unroll
            for (int ni = 0; ni < 4; ni++) {
                int n  = wn * 32 + ni * 8 + lr;
                int g0 = (((2 * kk)     ^ (n & 7)) << 2);
                int g1 = (((2 * kk + 1) ^ (n & 7)) << 2);
                b[ni][0] = Bs[n * 32 + g0 + lc];
                b[ni][1] = Bs[n * 32 + g1 + lc];
            }
#pragma unroll
            for (int mi = 0; mi < 4; mi++)
#pragma unroll
                for (int ni = 0; ni < 4; ni++) {
                    asm volatile(
                        "mma.sync.aligned.m16n8k8.row.col.f32.tf32.tf32.f32 "
                        "{%0,%1,%2,%3}, {%4,%5,%6,%7}, {%8,%9}, {%0,%1,%2,%3};"
                        : "+f"(acc[mi][ni][0]), "+f"(acc[mi][ni][1]),
                          "+f"(acc[mi][ni][2]), "+f"(acc[mi][ni][3])
                        : "r"(a[mi][0]), "r"(a[mi][1]), "r"(a[mi][2]), "r"(a[mi][3]),
                          "r"(b[ni][0]), "r"(b[ni][1]));
                }
        }
        __syncthreads();
    }

    // ---- epilogue ----
#pragma unroll
    for (int mi = 0; mi < 4; mi++) {
        int r = m0 + wm * 64 + mi * 16 + lr;
#pragma unroll
        for (int ni = 0; ni < 4; ni++) {
            int cb = n0 + wn * 32 + ni * 8 + 2 * lc;
            float b0 = 0.f, b1 = 0.f;
            if (BIAS) { b0 = bias[cb]; b1 = bias[cb + 1]; }
            C[(size_t)r * Ndim + cb]           = acc[mi][ni][0] + b0;
            C[(size_t)r * Ndim + cb + 1]       = acc[mi][ni][1] + b1;
            C[(size_t)(r + 8) * Ndim + cb]     = acc[mi][ni][2] + b0;
            C[(size_t)(r + 8) * Ndim + cb + 1] = acc[mi][ni][3] + b1;
        }
    }
}

// ---------------------------------------------------------------------------
// Flash attention (roles swapped: "query" = k-proj, "key" = q-proj).
// One block = (64 t-rows, one head, one batch). 256 threads, 4x4 microtiles.
// smem: Qt[64][64], Kt[64][65], Vt[64][64], Ps[64][65] = 66048 B dynamic.
// ---------------------------------------------------------------------------
__global__ void __launch_bounds__(256)
attn_kernel(const float* __restrict__ Kp, const float* __restrict__ Qp,
            const float* __restrict__ Vp, float* __restrict__ Out) {
    extern __shared__ float sm[];
    float* Qt = sm;                    // [64][64]
    float* Kt = Qt + 64 * 64;          // [64][65]
    float* Vt = Kt + 64 * 65;          // [64][64]
    float* Ps = Vt + 64 * 64;          // [64][65]

    const int tid = threadIdx.x;
    const int tx = tid & 15;
    const int ty = tid >> 4;
    const int tb = blockIdx.x;
    const int h = blockIdx.y;
    const int b = blockIdx.z;
    const float scale = 0.125f;        // HS^-0.5

    const float* kbase = Kp + (size_t)b * Tn * En + h * HSn;
    const float* qbase = Qp + (size_t)b * Tn * En + h * HSn;
    const float* vbase = Vp + (size_t)b * Tn * En + h * HSn;

    const int t0 = tb * 64;

#pragma unroll
    for (int i = 0; i < 16; i++) {
        int idx = tid + i * 256;
        int r = idx >> 6, c = idx & 63;
        Qt[r * 64 + c] = kbase[(size_t)(t0 + r) * En + c];
    }

    float m_i[4], l_i[4], o[4][4];
#pragma unroll
    for (int i = 0; i < 4; i++) {
        m_i[i] = -INFINITY;
        l_i[i] = 0.f;
#pragma unroll
        for (int j = 0; j < 4; j++) o[i][j] = 0.f;
    }

    for (int sb = 0; sb <= tb; sb++) {
        const int s0 = sb * 64;
        __syncthreads();
#pragma unroll
        for (int i = 0; i < 16; i++) {
            int idx = tid + i * 256;
            int r = idx >> 6, c = idx & 63;
            Kt[r * 65 + c] = qbase[(size_t)(s0 + r) * En + c];
            Vt[r * 64 + c] = vbase[(size_t)(s0 + r) * En + c];
        }
        __syncthreads();

        float s[4][4];
#pragma unroll
        for (int i = 0; i < 4; i++)
#pragma unroll
            for (int j = 0; j < 4; j++) s[i][j] = 0.f;
        for (int d = 0; d < 64; d++) {
            float a[4], bl[4];
#pragma unroll
            for (int i = 0; i < 4; i++) a[i] = Qt[(ty * 4 + i) * 64 + d];
#pragma unroll
            for (int j = 0; j < 4; j++) bl[j] = Kt[(tx * 4 + j) * 65 + d];
#pragma unroll
            for (int i = 0; i < 4; i++)
#pragma unroll
                for (int j = 0; j < 4; j++)
                    s[i][j] = fmaf(a[i], bl[j], s[i][j]);
        }

        const bool diag = (sb == tb);
#pragma unroll
        for (int i = 0; i < 4; i++) {
            int t = t0 + ty * 4 + i;
#pragma unroll
            for (int j = 0; j < 4; j++) {
                int ss = s0 + tx * 4 + j;
                s[i][j] *= scale;
                if (diag && ss > t) s[i][j] = -INFINITY;
            }
        }

#pragma unroll
        for (int i = 0; i < 4; i++) {
            float rm = fmaxf(fmaxf(s[i][0], s[i][1]), fmaxf(s[i][2], s[i][3]));
#pragma unroll
            for (int msk = 8; msk >= 1; msk >>= 1)
                rm = fmaxf(rm, __shfl_xor_sync(0xffffffffu, rm, msk));
            float mn = fmaxf(m_i[i], rm);
            float corr = __expf(m_i[i] - mn);
            float rs = 0.f;
#pragma unroll
            for (int j = 0; j < 4; j++) {
                float p = __expf(s[i][j] - mn);
                s[i][j] = p;
                rs += p;
            }
#pragma unroll
            for (int msk = 8; msk >= 1; msk >>= 1)
                rs += __shfl_xor_sync(0xffffffffu, rs, msk);
            l_i[i] = l_i[i] * corr + rs;
            m_i[i] = mn;
#pragma unroll
            for (int j = 0; j < 4; j++) o[i][j] *= corr;
        }

#pragma unroll
        for (int i = 0; i < 4; i++)
#pragma unroll
            for (int j = 0; j < 4; j++)
                Ps[(ty * 4 + i) * 65 + tx * 4 + j] = s[i][j];
        __syncthreads();

        for (int ss = 0; ss < 64; ss++) {
            float a[4], bl[4];
#pragma unroll
            for (int i = 0; i < 4; i++) a[i] = Ps[(ty * 4 + i) * 65 + ss];
#pragma unroll
            for (int j = 0; j < 4; j++) bl[j] = Vt[ss * 64 + tx * 4 + j];
#pragma unroll
            for (int i = 0; i < 4; i++)
#pragma unroll
                for (int j = 0; j < 4; j++)
                    o[i][j] = fmaf(a[i], bl[j], o[i][j]);
        }
    }

    float* obase = Out + (size_t)b * Tn * En + h * HSn;
#pragma unroll
    for (int i = 0; i < 4; i++) {
        float inv = 1.f / l_i[i];
#pragma unroll
        for (int j = 0; j < 4; j++)
            obase[(size_t)(t0 + ty * 4 + i) * En + tx * 4 + j] = o[i][j] * inv;
    }
}

// ---------------------------------------------------------------------------

static const int ATTN_SMEM = (64 * 64 + 64 * 65 + 64 * 64 + 64 * 65) * 4;  // 66048

extern "C" void kernel_launch(void* const* d_in, const int* in_sizes, int n_in,
                              void* d_out, int out_size) {
    (void)in_sizes; (void)n_in; (void)out_size;
    const float* x  = (const float*)d_in[0];
    const float* Wk = (const float*)d_in[1];
    const float* Wq = (const float*)d_in[2];
    const float* Wv = (const float*)d_in[3];
    const float* Wo = (const float*)d_in[4];
    const float* bo = (const float*)d_in[5];
    float* out = (float*)d_out;

    float *gk, *gq, *gv, *ga;
    cudaGetSymbolAddress((void**)&gk, g_k);
    cudaGetSymbolAddress((void**)&gq, g_q);
    cudaGetSymbolAddress((void**)&gv, g_v);
    cudaGetSymbolAddress((void**)&ga, g_att);

    cudaFuncSetAttribute(attn_kernel,
                         cudaFuncAttributeMaxDynamicSharedMemorySize, ATTN_SMEM);

    dim3 gproj(Mn / 128, En / 128);
    gemm_tc<false><<<gproj, 256>>>(x, Wk, nullptr, gk, En, En);
    gemm_tc<false><<<gproj, 256>>>(x, Wq, nullptr, gq, En, En);
    gemm_tc<false><<<gproj, 256>>>(x, Wv, nullptr, gv, En, En);

    dim3 gattn(Tn / 64, Hn, Bn);
    attn_kernel<<<gattn, 256, ATTN_SMEM>>>(gk, gq, gv, ga);

    gemm_tc<true><<<gproj, 256>>>(ga, Wo, bo, out, En, En);
}

// round 4
// speedup vs baseline: 3.9645x; 1.6654x over previous
#include <cuda_runtime.h>
#include <math.h>

#define Bn 4
#define Tn 2048
#define En 1024
#define Hn 16
#define HSn 64
#define Mn (Bn * Tn)   // 8192
#define STR 68         // padded smem row stride (floats)

// Scratch buffers (device globals: allocation-free rule)
__device__ float g_k[Mn * En];
__device__ float g_q[Mn * En];
__device__ float g_v[Mn * En];
__device__ float g_att[Mn * En];

__device__ __forceinline__ unsigned f2tf32(float f) {
    unsigned r;
    asm("cvt.rna.tf32.f32 %0, %1;" : "=r"(r) : "f"(f));
    return r;
}

__device__ __forceinline__ void mma_tf32(float* c, const unsigned* a, const unsigned* b) {
    asm volatile(
        "mma.sync.aligned.m16n8k8.row.col.f32.tf32.tf32.f32 "
        "{%0,%1,%2,%3}, {%4,%5,%6,%7}, {%8,%9}, {%0,%1,%2,%3};"
        : "+f"(c[0]), "+f"(c[1]), "+f"(c[2]), "+f"(c[3])
        : "r"(a[0]), "r"(a[1]), "r"(a[2]), "r"(a[3]), "r"(b[0]), "r"(b[1]));
}

// ---------------------------------------------------------------------------
// TF32 tensor-core NT GEMM: C[M,N] = A[M,K] @ Bm[N,K]^T (+ bias[n])
// 128x128 tile, BK=32, 256 threads, 8 warps of 64x32, XOR-swizzled smem.
// ---------------------------------------------------------------------------
template <bool BIAS>
__global__ void __launch_bounds__(256, 2)
gemm_tc(const float* __restrict__ A, const float* __restrict__ Bm,
        const float* __restrict__ bias, float* __restrict__ C,
        int Kdim, int Ndim) {
    __shared__ unsigned As[128 * 32];
    __shared__ unsigned Bs[128 * 32];

    const int tid  = threadIdx.x;
    const int lane = tid & 31;
    const int warp = tid >> 5;
    const int wm   = warp >> 2;
    const int wn   = warp & 3;
    const int m0   = blockIdx.x * 128;
    const int n0   = blockIdx.y * 128;

    float acc[4][4][4];
#pragma unroll
    for (int mi = 0; mi < 4; mi++)
#pragma unroll
        for (int ni = 0; ni < 4; ni++)
#pragma unroll
            for (int r = 0; r < 4; r++) acc[mi][ni][r] = 0.f;

    const int lr = lane >> 2;
    const int lc = lane & 3;

    for (int k0 = 0; k0 < Kdim; k0 += 32) {
#pragma unroll
        for (int i = 0; i < 4; i++) {
            int f   = tid + i * 256;
            int row = f >> 3;
            int c4  = f & 7;
            int sg  = ((c4 ^ (row & 7)) << 2);
            float4 av = *(const float4*)(A  + (size_t)(m0 + row) * Kdim + k0 + c4 * 4);
            float4 bv = *(const float4*)(Bm + (size_t)(n0 + row) * Kdim + k0 + c4 * 4);
            uint4 at = make_uint4(f2tf32(av.x), f2tf32(av.y), f2tf32(av.z), f2tf32(av.w));
            uint4 bt = make_uint4(f2tf32(bv.x), f2tf32(bv.y), f2tf32(bv.z), f2tf32(bv.w));
            *(uint4*)(&As[row * 32 + sg]) = at;
            *(uint4*)(&Bs[row * 32 + sg]) = bt;
        }
        __syncthreads();

#pragma unroll
        for (int kk = 0; kk < 4; kk++) {
            unsigned a[4][4], b[4][2];
#pragma unroll
            for (int mi = 0; mi < 4; mi++) {
                int r  = wm * 64 + mi * 16 + lr;
                int g0 = (((2 * kk)     ^ (r & 7)) << 2);
                int g1 = (((2 * kk + 1) ^ (r & 7)) << 2);
                a[mi][0] = As[r * 32 + g0 + lc];
                a[mi][1] = As[(r + 8) * 32 + g0 + lc];
                a[mi][2] = As[r * 32 + g1 + lc];
                a[mi][3] = As[(r + 8) * 32 + g1 + lc];
            }
#pragma unroll
            for (int ni = 0; ni < 4; ni++) {
                int n  = wn * 32 + ni * 8 + lr;
                int g0 = (((2 * kk)     ^ (n & 7)) << 2);
                int g1 = (((2 * kk + 1) ^ (n & 7)) << 2);
                b[ni][0] = Bs[n * 32 + g0 + lc];
                b[ni][1] = Bs[n * 32 + g1 + lc];
            }
#pragma unroll
            for (int mi = 0; mi < 4; mi++)
#pragma unroll
                for (int ni = 0; ni < 4; ni++)
                    mma_tf32(acc[mi][ni], a[mi], b[ni]);
        }
        __syncthreads();
    }

#pragma unroll
    for (int mi = 0; mi < 4; mi++) {
        int r = m0 + wm * 64 + mi * 16 + lr;
#pragma unroll
        for (int ni = 0; ni < 4; ni++) {
            int cb = n0 + wn * 32 + ni * 8 + 2 * lc;
            float b0 = 0.f, b1 = 0.f;
            if (BIAS) { b0 = bias[cb]; b1 = bias[cb + 1]; }
            C[(size_t)r * Ndim + cb]           = acc[mi][ni][0] + b0;
            C[(size_t)r * Ndim + cb + 1]       = acc[mi][ni][1] + b1;
            C[(size_t)(r + 8) * Ndim + cb]     = acc[mi][ni][2] + b0;
            C[(size_t)(r + 8) * Ndim + cb + 1] = acc[mi][ni][3] + b1;
        }
    }
}

// ---------------------------------------------------------------------------
// TF32 tensor-core flash attention (roles swapped: "query"=k-proj, "key"=q-proj)
// CTA: 128 t-rows x one (b,h). 8 warps x 16 rows. s tiled by 64, causal.
// smem tiles row-major, stride 68 floats (conflict-free fragment loads).
// ---------------------------------------------------------------------------
__global__ void __launch_bounds__(256)
attn_tc(const float* __restrict__ Kp, const float* __restrict__ Qp,
        const float* __restrict__ Vp, float* __restrict__ Out) {
    extern __shared__ float smx[];
    float* Qt = smx;                   // [128][STR]
    float* Kt = Qt + 128 * STR;        // [64][STR]
    float* Vt = Kt + 64 * STR;         // [64][STR]
    float* Ps = Vt + 64 * STR;         // [128][STR]

    const int tid  = threadIdx.x;
    const int lane = tid & 31;
    const int warp = tid >> 5;
    const int lr   = lane >> 2;
    const int lc   = lane & 3;

    const int tb = (gridDim.x - 1) - blockIdx.x;   // heavy tiles first
    const int h  = blockIdx.y;
    const int b  = blockIdx.z;
    const int t0 = tb * 128;

    const float* kbase = Kp + (size_t)b * Tn * En + h * HSn;  // attention "Q"
    const float* qbase = Qp + (size_t)b * Tn * En + h * HSn;  // attention "K"
    const float* vbase = Vp + (size_t)b * Tn * En + h * HSn;

    // Load Q tile (scale folded in), tf32-convert
#pragma unroll
    for (int i = 0; i < 8; i++) {
        int f = tid + i * 256;             // 0..2047
        int r = f >> 4, c = f & 15;
        float4 v = *(const float4*)(kbase + (size_t)(t0 + r) * En + c * 4);
        uint4 t = make_uint4(f2tf32(v.x * 0.125f), f2tf32(v.y * 0.125f),
                             f2tf32(v.z * 0.125f), f2tf32(v.w * 0.125f));
        *(uint4*)(Qt + r * STR + c * 4) = t;
    }

    float o[8][4];
#pragma unroll
    for (int ni = 0; ni < 8; ni++)
#pragma unroll
        for (int r = 0; r < 4; r++) o[ni][r] = 0.f;
    float m0f = -INFINITY, m1f = -INFINITY, l0 = 0.f, l1 = 0.f;

    const unsigned* Qu = (const unsigned*)Qt;
    const unsigned* Ku = (const unsigned*)Kt;
    const unsigned* Vu = (const unsigned*)Vt;
    unsigned* Pu = (unsigned*)Ps;

    const int row0 = t0 + warp * 16 + lr;
    const int row1 = row0 + 8;
    const int nsb = 2 * tb + 2;

    for (int sb = 0; sb < nsb; sb++) {
        const int s0 = sb * 64;
        __syncthreads();   // prior-iter S/PV reads of Kt/Vt complete
#pragma unroll
        for (int i = 0; i < 4; i++) {
            int f = tid + i * 256;         // 0..1023
            int r = f >> 4, c = f & 15;
            float4 kv = *(const float4*)(qbase + (size_t)(s0 + r) * En + c * 4);
            float4 vv = *(const float4*)(vbase + (size_t)(s0 + r) * En + c * 4);
            *(uint4*)(Kt + r * STR + c * 4) =
                make_uint4(f2tf32(kv.x), f2tf32(kv.y), f2tf32(kv.z), f2tf32(kv.w));
            *(uint4*)(Vt + r * STR + c * 4) =
                make_uint4(f2tf32(vv.x), f2tf32(vv.y), f2tf32(vv.z), f2tf32(vv.w));
        }
        __syncthreads();

        // ---- S = Q @ K^T ----
        float s[8][4];
#pragma unroll
        for (int ni = 0; ni < 8; ni++)
#pragma unroll
            for (int r = 0; r < 4; r++) s[ni][r] = 0.f;

#pragma unroll
        for (int kk = 0; kk < 8; kk++) {
            unsigned a[4];
            int qb = (warp * 16 + lr) * STR + kk * 8 + lc;
            a[0] = Qu[qb];
            a[1] = Qu[qb + 8 * STR];
            a[2] = Qu[qb + 4];
            a[3] = Qu[qb + 8 * STR + 4];
#pragma unroll
            for (int ni = 0; ni < 8; ni++) {
                unsigned bfr[2];
                int kb = (ni * 8 + lr) * STR + kk * 8 + lc;
                bfr[0] = Ku[kb];
                bfr[1] = Ku[kb + 4];
                mma_tf32(s[ni], a, bfr);
            }
        }

        // ---- causal mask (only for diagonal-adjacent s-blocks) ----
        if (s0 + 63 > t0) {
#pragma unroll
            for (int ni = 0; ni < 8; ni++) {
                int c0 = s0 + ni * 8 + 2 * lc;
                if (c0 > row0)     s[ni][0] = -INFINITY;
                if (c0 + 1 > row0) s[ni][1] = -INFINITY;
                if (c0 > row1)     s[ni][2] = -INFINITY;
                if (c0 + 1 > row1) s[ni][3] = -INFINITY;
            }
        }

        // ---- online softmax (rows within quad: shfl_xor 1,2) ----
        float rm0 = -INFINITY, rm1 = -INFINITY;
#pragma unroll
        for (int ni = 0; ni < 8; ni++) {
            rm0 = fmaxf(rm0, fmaxf(s[ni][0], s[ni][1]));
            rm1 = fmaxf(rm1, fmaxf(s[ni][2], s[ni][3]));
        }
        rm0 = fmaxf(rm0, __shfl_xor_sync(0xffffffffu, rm0, 1));
        rm0 = fmaxf(rm0, __shfl_xor_sync(0xffffffffu, rm0, 2));
        rm1 = fmaxf(rm1, __shfl_xor_sync(0xffffffffu, rm1, 1));
        rm1 = fmaxf(rm1, __shfl_xor_sync(0xffffffffu, rm1, 2));

        float mn0 = fmaxf(m0f, rm0);
        float mn1 = fmaxf(m1f, rm1);
        float corr0 = __expf(m0f - mn0);
        float corr1 = __expf(m1f - mn1);

        float rs0 = 0.f, rs1 = 0.f;
        unsigned* pr0 = Pu + (warp * 16 + lr) * STR + 2 * lc;
        unsigned* pr1 = pr0 + 8 * STR;
#pragma unroll
        for (int ni = 0; ni < 8; ni++) {
            float p0 = __expf(s[ni][0] - mn0);
            float p1 = __expf(s[ni][1] - mn0);
            float p2 = __expf(s[ni][2] - mn1);
            float p3 = __expf(s[ni][3] - mn1);
            rs0 += p0 + p1;
            rs1 += p2 + p3;
            pr0[ni * 8]     = f2tf32(p0);
            pr0[ni * 8 + 1] = f2tf32(p1);
            pr1[ni * 8]     = f2tf32(p2);
            pr1[ni * 8 + 1] = f2tf32(p3);
        }
        rs0 += __shfl_xor_sync(0xffffffffu, rs0, 1);
        rs0 += __shfl_xor_sync(0xffffffffu, rs0, 2);
        rs1 += __shfl_xor_sync(0xffffffffu, rs1, 1);
        rs1 += __shfl_xor_sync(0xffffffffu, rs1, 2);

        l0 = l0 * corr0 + rs0;
        l1 = l1 * corr1 + rs1;
        m0f = mn0;
        m1f = mn1;
#pragma unroll
        for (int ni = 0; ni < 8; ni++) {
            o[ni][0] *= corr0;
            o[ni][1] *= corr0;
            o[ni][2] *= corr1;
            o[ni][3] *= corr1;
        }
        __syncwarp();   // each warp reads back ONLY its own P rows

        // ---- O += P @ V ----
#pragma unroll
        for (int kk = 0; kk < 8; kk++) {
            unsigned a[4];
            int pb = (warp * 16 + lr) * STR + kk * 8 + lc;
            a[0] = Pu[pb];
            a[1] = Pu[pb + 8 * STR];
            a[2] = Pu[pb + 4];
            a[3] = Pu[pb + 8 * STR + 4];
#pragma unroll
            for (int ni = 0; ni < 8; ni++) {
                unsigned bfr[2];
                int vb = (kk * 8 + lc) * STR + ni * 8 + lr;
                bfr[0] = Vu[vb];
                bfr[1] = Vu[vb + 4 * STR];
                mma_tf32(o[ni], a, bfr);
            }
        }
    }

    // ---- epilogue ----
    float inv0 = 1.f / l0;
    float inv1 = 1.f / l1;
    float* ob = Out + (size_t)b * Tn * En + h * HSn;
#pragma unroll
    for (int ni = 0; ni < 8; ni++) {
        int c = ni * 8 + 2 * lc;
        *(float2*)(ob + (size_t)row0 * En + c) =
            make_float2(o[ni][0] * inv0, o[ni][1] * inv0);
        *(float2*)(ob + (size_t)row1 * En + c) =
            make_float2(o[ni][2] * inv1, o[ni][3] * inv1);
    }
}

// ---------------------------------------------------------------------------

static const int ATTN_SMEM = (128 + 64 + 64 + 128) * STR * 4;  // 104448

extern "C" void kernel_launch(void* const* d_in, const int* in_sizes, int n_in,
                              void* d_out, int out_size) {
    (void)in_sizes; (void)n_in; (void)out_size;
    const float* x  = (const float*)d_in[0];
    const float* Wk = (const float*)d_in[1];
    const float* Wq = (const float*)d_in[2];
    const float* Wv = (const float*)d_in[3];
    const float* Wo = (const float*)d_in[4];
    const float* bo = (const float*)d_in[5];
    float* out = (float*)d_out;

    float *gk, *gq, *gv, *ga;
    cudaGetSymbolAddress((void**)&gk, g_k);
    cudaGetSymbolAddress((void**)&gq, g_q);
    cudaGetSymbolAddress((void**)&gv, g_v);
    cudaGetSymbolAddress((void**)&ga, g_att);

    cudaFuncSetAttribute(attn_tc,
                         cudaFuncAttributeMaxDynamicSharedMemorySize, ATTN_SMEM);

    dim3 gproj(Mn / 128, En / 128);
    gemm_tc<false><<<gproj, 256>>>(x, Wk, nullptr, gk, En, En);
    gemm_tc<false><<<gproj, 256>>>(x, Wq, nullptr, gq, En, En);
    gemm_tc<false><<<gproj, 256>>>(x, Wv, nullptr, gv, En, En);

    dim3 gattn(Tn / 128, Hn, Bn);
    attn_tc<<<gattn, 256, ATTN_SMEM>>>(gk, gq, gv, ga);

    gemm_tc<true><<<gproj, 256>>>(ga, Wo, bo, out, En, En);
}

// round 5
// speedup vs baseline: 4.3169x; 1.0889x over previous
#include <cuda_runtime.h>
#include <math.h>

#define Bn 4
#define Tn 2048
#define En 1024
#define Hn 16
#define HSn 64
#define Mn (Bn * Tn)   // 8192
#define STR 68         // smem row stride for Q/K/P tiles (floats), ==4 mod 32
#define SV  72         // smem row stride for V tile (floats), ==8 mod 32

// Scratch buffers (device globals: allocation-free rule)
__device__ float g_k[Mn * En];
__device__ float g_q[Mn * En];
__device__ float g_v[Mn * En];
__device__ float g_att[Mn * En];

__device__ __forceinline__ unsigned f2tf32(float f) {
    unsigned r;
    asm("cvt.rna.tf32.f32 %0, %1;" : "=r"(r) : "f"(f));
    return r;
}

__device__ __forceinline__ void mma_tf32(float* c, const unsigned* a, const unsigned* b) {
    asm volatile(
        "mma.sync.aligned.m16n8k8.row.col.f32.tf32.tf32.f32 "
        "{%0,%1,%2,%3}, {%4,%5,%6,%7}, {%8,%9}, {%0,%1,%2,%3};"
        : "+f"(c[0]), "+f"(c[1]), "+f"(c[2]), "+f"(c[3])
        : "r"(a[0]), "r"(a[1]), "r"(a[2]), "r"(a[3]), "r"(b[0]), "r"(b[1]));
}

__device__ __forceinline__ void ldm_x4(unsigned* r, unsigned addr) {
    asm volatile("ldmatrix.sync.aligned.m8n8.x4.shared.b16 {%0,%1,%2,%3}, [%4];"
                 : "=r"(r[0]), "=r"(r[1]), "=r"(r[2]), "=r"(r[3]) : "r"(addr));
}

// ---------------------------------------------------------------------------
// TF32 tensor-core NT GEMM: C[M,N] = A[M,K] @ Bm[N,K]^T (+ bias[n])
// POST: 0 = plain fp32 store; 1 = tf32-rounded store; 2 = *0.125 then tf32-round
// ---------------------------------------------------------------------------
template <bool BIAS, int POST>
__global__ void __launch_bounds__(256, 2)
gemm_tc(const float* __restrict__ A, const float* __restrict__ Bm,
        const float* __restrict__ bias, float* __restrict__ C,
        int Kdim, int Ndim) {
    __shared__ unsigned As[128 * 32];
    __shared__ unsigned Bs[128 * 32];

    const int tid  = threadIdx.x;
    const int lane = tid & 31;
    const int warp = tid >> 5;
    const int wm   = warp >> 2;
    const int wn   = warp & 3;
    const int m0   = blockIdx.x * 128;
    const int n0   = blockIdx.y * 128;

    float acc[4][4][4];
#pragma unroll
    for (int mi = 0; mi < 4; mi++)
#pragma unroll
        for (int ni = 0; ni < 4; ni++)
#pragma unroll
            for (int r = 0; r < 4; r++) acc[mi][ni][r] = 0.f;

    const int lr = lane >> 2;
    const int lc = lane & 3;

    for (int k0 = 0; k0 < Kdim; k0 += 32) {
#pragma unroll
        for (int i = 0; i < 4; i++) {
            int f   = tid + i * 256;
            int row = f >> 3;
            int c4  = f & 7;
            int sg  = ((c4 ^ (row & 7)) << 2);
            float4 av = *(const float4*)(A  + (size_t)(m0 + row) * Kdim + k0 + c4 * 4);
            float4 bv = *(const float4*)(Bm + (size_t)(n0 + row) * Kdim + k0 + c4 * 4);
            uint4 at = make_uint4(f2tf32(av.x), f2tf32(av.y), f2tf32(av.z), f2tf32(av.w));
            uint4 bt = make_uint4(f2tf32(bv.x), f2tf32(bv.y), f2tf32(bv.z), f2tf32(bv.w));
            *(uint4*)(&As[row * 32 + sg]) = at;
            *(uint4*)(&Bs[row * 32 + sg]) = bt;
        }
        __syncthreads();

#pragma unroll
        for (int kk = 0; kk < 4; kk++) {
            unsigned a[4][4], b[4][2];
#pragma unroll
            for (int mi = 0; mi < 4; mi++) {
                int r  = wm * 64 + mi * 16 + lr;
                int g0 = (((2 * kk)     ^ (r & 7)) << 2);
                int g1 = (((2 * kk + 1) ^ (r & 7)) << 2);
                a[mi][0] = As[r * 32 + g0 + lc];
                a[mi][1] = As[(r + 8) * 32 + g0 + lc];
                a[mi][2] = As[r * 32 + g1 + lc];
                a[mi][3] = As[(r + 8) * 32 + g1 + lc];
            }
#pragma unroll
            for (int ni = 0; ni < 4; ni++) {
                int n  = wn * 32 + ni * 8 + lr;
                int g0 = (((2 * kk)     ^ (n & 7)) << 2);
                int g1 = (((2 * kk + 1) ^ (n & 7)) << 2);
                b[ni][0] = Bs[n * 32 + g0 + lc];
                b[ni][1] = Bs[n * 32 + g1 + lc];
            }
#pragma unroll
            for (int mi = 0; mi < 4; mi++)
#pragma unroll
                for (int ni = 0; ni < 4; ni++)
                    mma_tf32(acc[mi][ni], a[mi], b[ni]);
        }
        __syncthreads();
    }

#pragma unroll
    for (int mi = 0; mi < 4; mi++) {
        int r = m0 + wm * 64 + mi * 16 + lr;
#pragma unroll
        for (int ni = 0; ni < 4; ni++) {
            int cb = n0 + wn * 32 + ni * 8 + 2 * lc;
            float b0 = 0.f, b1 = 0.f;
            if (BIAS) { b0 = bias[cb]; b1 = bias[cb + 1]; }
            float v00 = acc[mi][ni][0] + b0, v01 = acc[mi][ni][1] + b1;
            float v10 = acc[mi][ni][2] + b0, v11 = acc[mi][ni][3] + b1;
            if (POST == 2) { v00 *= 0.125f; v01 *= 0.125f; v10 *= 0.125f; v11 *= 0.125f; }
            if (POST >= 1) {
                v00 = __uint_as_float(f2tf32(v00));
                v01 = __uint_as_float(f2tf32(v01));
                v10 = __uint_as_float(f2tf32(v10));
                v11 = __uint_as_float(f2tf32(v11));
            }
            C[(size_t)r * Ndim + cb]           = v00;
            C[(size_t)r * Ndim + cb + 1]       = v01;
            C[(size_t)(r + 8) * Ndim + cb]     = v10;
            C[(size_t)(r + 8) * Ndim + cb + 1] = v11;
        }
    }
}

// ---------------------------------------------------------------------------
// TF32 tensor-core flash attention (roles swapped: "query"=k-proj, "key"=q-proj)
// Inputs are pre-rounded to tf32 (and pre-scaled for Q) by the projection GEMMs.
// CTA: 128 t-rows x one (b,h). 8 warps x 16 rows. s tiled by 64, causal.
// Q/K/P tiles stride STR=68; V tile stride SV=72 (both conflict-free patterns).
// Fragment loads via ldmatrix.m8n8.x4 (b16 view == tf32 b32 fragments).
// ---------------------------------------------------------------------------
__global__ void __launch_bounds__(256)
attn_tc(const float* __restrict__ Kp, const float* __restrict__ Qp,
        const float* __restrict__ Vp, float* __restrict__ Out) {
    extern __shared__ float smx[];
    float* Qt = smx;                   // [128][STR]
    float* Kt = Qt + 128 * STR;        // [64][STR]
    float* Vt = Kt + 64 * STR;         // [64][SV]
    float* Ps = Vt + 64 * SV;          // [128][STR]

    const int tid  = threadIdx.x;
    const int lane = tid & 31;
    const int warp = tid >> 5;
    const int lr   = lane >> 2;
    const int lc   = lane & 3;

    const int tb = (gridDim.x - 1) - blockIdx.x;   // heavy tiles first
    const int h  = blockIdx.y;
    const int b  = blockIdx.z;
    const int t0 = tb * 128;

    const float* kbase = Kp + (size_t)b * Tn * En + h * HSn;  // attention "Q"
    const float* qbase = Qp + (size_t)b * Tn * En + h * HSn;  // attention "K"
    const float* vbase = Vp + (size_t)b * Tn * En + h * HSn;

    // Load Q tile (already tf32-rounded & scaled) — raw copy
#pragma unroll
    for (int i = 0; i < 8; i++) {
        int f = tid + i * 256;             // 0..2047
        int r = f >> 4, c = f & 15;
        *(float4*)(Qt + r * STR + c * 4) =
            *(const float4*)(kbase + (size_t)(t0 + r) * En + c * 4);
    }

    float o[8][4];
#pragma unroll
    for (int ni = 0; ni < 8; ni++)
#pragma unroll
        for (int r = 0; r < 4; r++) o[ni][r] = 0.f;
    float m0f = -INFINITY, m1f = -INFINITY, l0 = 0.f, l1 = 0.f;

    const unsigned* Vu = (const unsigned*)Vt;
    unsigned* Pu = (unsigned*)Ps;

    // ldmatrix per-lane base addresses
    const int lm  = lane >> 3;          // matrix index 0..3
    const int lrw = lane & 7;           // row within matrix
    const unsigned qsm = (unsigned)__cvta_generic_to_shared(Qt);
    const unsigned ksm = (unsigned)__cvta_generic_to_shared(Kt);
    const unsigned psm = (unsigned)__cvta_generic_to_shared(Ps);
    // A-frag (Q/P): m0=rows0-7 col0, m1=rows8-15 col0, m2=rows0-7 col+4, m3=rows8-15 col+4
    const unsigned qa0 = qsm + ((warp * 16 + (lm & 1) * 8 + lrw) * STR + (lm >> 1) * 4) * 4;
    const unsigned pa0 = psm + ((warp * 16 + (lm & 1) * 8 + lrw) * STR + (lm >> 1) * 4) * 4;
    // B-frag (K): m0=rows(ni*8) col0, m1=rows(ni*8) col+4, m2=rows((ni+1)*8) col0, m3=+4
    const unsigned ka0 = ksm + (((lm >> 1) * 8 + lrw) * STR + (lm & 1) * 4) * 4;

    const int row0 = t0 + warp * 16 + lr;
    const int row1 = row0 + 8;
    const int nsb = 2 * tb + 2;

    for (int sb = 0; sb < nsb; sb++) {
        const int s0 = sb * 64;
        __syncthreads();   // prior-iter S/PV reads of Kt/Vt complete
#pragma unroll
        for (int i = 0; i < 4; i++) {
            int f = tid + i * 256;         // 0..1023
            int r = f >> 4, c = f & 15;
            *(float4*)(Kt + r * STR + c * 4) =
                *(const float4*)(qbase + (size_t)(s0 + r) * En + c * 4);
            *(float4*)(Vt + r * SV + c * 4) =
                *(const float4*)(vbase + (size_t)(s0 + r) * En + c * 4);
        }
        __syncthreads();

        // ---- S = Q @ K^T ----
        float s[8][4];
#pragma unroll
        for (int ni = 0; ni < 8; ni++)
#pragma unroll
            for (int r = 0; r < 4; r++) s[ni][r] = 0.f;

#pragma unroll
        for (int kk = 0; kk < 8; kk++) {
            unsigned aq[4];
            ldm_x4(aq, qa0 + kk * 32);
#pragma unroll
            for (int nip = 0; nip < 4; nip++) {
                unsigned kf[4];
                ldm_x4(kf, ka0 + nip * (16 * STR * 4) + kk * 32);
                mma_tf32(s[2 * nip],     aq, kf);
                mma_tf32(s[2 * nip + 1], aq, kf + 2);
            }
        }

        // ---- causal mask (only for diagonal-adjacent s-blocks) ----
        if (s0 + 63 > t0) {
#pragma unroll
            for (int ni = 0; ni < 8; ni++) {
                int c0 = s0 + ni * 8 + 2 * lc;
                if (c0 > row0)     s[ni][0] = -INFINITY;
                if (c0 + 1 > row0) s[ni][1] = -INFINITY;
                if (c0 > row1)     s[ni][2] = -INFINITY;
                if (c0 + 1 > row1) s[ni][3] = -INFINITY;
            }
        }

        // ---- online softmax (rows within quad: shfl_xor 1,2) ----
        float rm0 = -INFINITY, rm1 = -INFINITY;
#pragma unroll
        for (int ni = 0; ni < 8; ni++) {
            rm0 = fmaxf(rm0, fmaxf(s[ni][0], s[ni][1]));
            rm1 = fmaxf(rm1, fmaxf(s[ni][2], s[ni][3]));
        }
        rm0 = fmaxf(rm0, __shfl_xor_sync(0xffffffffu, rm0, 1));
        rm0 = fmaxf(rm0, __shfl_xor_sync(0xffffffffu, rm0, 2));
        rm1 = fmaxf(rm1, __shfl_xor_sync(0xffffffffu, rm1, 1));
        rm1 = fmaxf(rm1, __shfl_xor_sync(0xffffffffu, rm1, 2));

        float mn0 = fmaxf(m0f, rm0);
        float mn1 = fmaxf(m1f, rm1);
        float corr0 = __expf(m0f - mn0);
        float corr1 = __expf(m1f - mn1);

        float rs0 = 0.f, rs1 = 0.f;
        unsigned* pr0 = Pu + (warp * 16 + lr) * STR + 2 * lc;
        unsigned* pr1 = pr0 + 8 * STR;
#pragma unroll
        for (int ni = 0; ni < 8; ni++) {
            float p0 = __expf(s[ni][0] - mn0);
            float p1 = __expf(s[ni][1] - mn0);
            float p2 = __expf(s[ni][2] - mn1);
            float p3 = __expf(s[ni][3] - mn1);
            rs0 += p0 + p1;
            rs1 += p2 + p3;
            pr0[ni * 8]     = f2tf32(p0);
            pr0[ni * 8 + 1] = f2tf32(p1);
            pr1[ni * 8]     = f2tf32(p2);
            pr1[ni * 8 + 1] = f2tf32(p3);
        }
        rs0 += __shfl_xor_sync(0xffffffffu, rs0, 1);
        rs0 += __shfl_xor_sync(0xffffffffu, rs0, 2);
        rs1 += __shfl_xor_sync(0xffffffffu, rs1, 1);
        rs1 += __shfl_xor_sync(0xffffffffu, rs1, 2);

        l0 = l0 * corr0 + rs0;
        l1 = l1 * corr1 + rs1;
        m0f = mn0;
        m1f = mn1;
#pragma unroll
        for (int ni = 0; ni < 8; ni++) {
            o[ni][0] *= corr0;
            o[ni][1] *= corr0;
            o[ni][2] *= corr1;
            o[ni][3] *= corr1;
        }
        __syncwarp();   // each warp reads back ONLY its own P rows

        // ---- O += P @ V ----
#pragma unroll
        for (int kk = 0; kk < 8; kk++) {
            unsigned ap[4];
            ldm_x4(ap, pa0 + kk * 32);
#pragma unroll
            for (int ni = 0; ni < 8; ni++) {
                unsigned bfr[2];
                int vb = (kk * 8 + lc) * SV + ni * 8 + lr;
                bfr[0] = Vu[vb];
                bfr[1] = Vu[vb + 4 * SV];
                mma_tf32(o[ni], ap, bfr);
            }
        }
    }

    // ---- epilogue ----
    float inv0 = 1.f / l0;
    float inv1 = 1.f / l1;
    float* ob = Out + (size_t)b * Tn * En + h * HSn;
#pragma unroll
    for (int ni = 0; ni < 8; ni++) {
        int c = ni * 8 + 2 * lc;
        *(float2*)(ob + (size_t)row0 * En + c) =
            make_float2(o[ni][0] * inv0, o[ni][1] * inv0);
        *(float2*)(ob + (size_t)row1 * En + c) =
            make_float2(o[ni][2] * inv1, o[ni][3] * inv1);
    }
}

// ---------------------------------------------------------------------------

static const int ATTN_SMEM = (128 * STR + 64 * STR + 64 * SV + 128 * STR) * 4;  // 105472

extern "C" void kernel_launch(void* const* d_in, const int* in_sizes, int n_in,
                              void* d_out, int out_size) {
    (void)in_sizes; (void)n_in; (void)out_size;
    const float* x  = (const float*)d_in[0];
    const float* Wk = (const float*)d_in[1];
    const float* Wq = (const float*)d_in[2];
    const float* Wv = (const float*)d_in[3];
    const float* Wo = (const float*)d_in[4];
    const float* bo = (const float*)d_in[5];
    float* out = (float*)d_out;

    float *gk, *gq, *gv, *ga;
    cudaGetSymbolAddress((void**)&gk, g_k);
    cudaGetSymbolAddress((void**)&gq, g_q);
    cudaGetSymbolAddress((void**)&gv, g_v);
    cudaGetSymbolAddress((void**)&ga, g_att);

    cudaFuncSetAttribute(attn_tc,
                         cudaFuncAttributeMaxDynamicSharedMemorySize, ATTN_SMEM);

    dim3 gproj(Mn / 128, En / 128);
    // k-projection: pre-scale by 0.125 (exact) + tf32 pre-round
    gemm_tc<false, 2><<<gproj, 256>>>(x, Wk, nullptr, gk, En, En);
    // q/v-projections: tf32 pre-round
    gemm_tc<false, 1><<<gproj, 256>>>(x, Wq, nullptr, gq, En, En);
    gemm_tc<false, 1><<<gproj, 256>>>(x, Wv, nullptr, gv, En, En);

    dim3 gattn(Tn / 128, Hn, Bn);
    attn_tc<<<gattn, 256, ATTN_SMEM>>>(gk, gq, gv, ga);

    gemm_tc<true, 0><<<gproj, 256>>>(ga, Wo, bo, out, En, En);
}

// round 6
// speedup vs baseline: 7.7345x; 1.7917x over previous
#include <cuda_runtime.h>
#include <cuda_fp16.h>
#include <math.h>

#define Bn 4
#define Tn 2048
#define En 1024
#define Hn 16
#define HSn 64
#define Mn (Bn * Tn)   // 8192

// Scratch buffers (device globals: allocation-free rule). fp16 intermediates.
__device__ __half g_k[Mn * En];
__device__ __half g_q[Mn * En];
__device__ __half g_v[Mn * En];
__device__ __half g_att[Mn * En];

__device__ __forceinline__ void mma_f16(float* c, const unsigned* a, const unsigned* b) {
    asm volatile(
        "mma.sync.aligned.m16n8k16.row.col.f32.f16.f16.f32 "
        "{%0,%1,%2,%3}, {%4,%5,%6,%7}, {%8,%9}, {%0,%1,%2,%3};"
        : "+f"(c[0]), "+f"(c[1]), "+f"(c[2]), "+f"(c[3])
        : "r"(a[0]), "r"(a[1]), "r"(a[2]), "r"(a[3]), "r"(b[0]), "r"(b[1]));
}
__device__ __forceinline__ void ldm_x4(unsigned* r, unsigned a) {
    asm volatile("ldmatrix.sync.aligned.m8n8.x4.shared.b16 {%0,%1,%2,%3}, [%4];"
                 : "=r"(r[0]), "=r"(r[1]), "=r"(r[2]), "=r"(r[3]) : "r"(a));
}
__device__ __forceinline__ void ldm_x4_t(unsigned* r, unsigned a) {
    asm volatile("ldmatrix.sync.aligned.m8n8.x4.trans.shared.b16 {%0,%1,%2,%3}, [%4];"
                 : "=r"(r[0]), "=r"(r[1]), "=r"(r[2]), "=r"(r[3]) : "r"(a));
}
__device__ __forceinline__ unsigned h2u(__half2 h) {
    return *reinterpret_cast<unsigned*>(&h);
}

// ===========================================================================
// Shared GEMM body pieces (fp16 m16n8k16, 128x128 tile, BK=32, 8 warps 64x32)
// smem rows: 32 halves = 64B = 4 x 16B groups; swizzle: phys = g ^ ((row>>1)&3)
// ===========================================================================

// Load one 128x32 fp32 tile -> fp16 smem (swizzled). 4 iters of 256 threads.
__device__ __forceinline__ void load_tile_f32(__half* S, const float* A,
                                              int base, int Kdim, int k0, int tid) {
#pragma unroll
    for (int i = 0; i < 4; i++) {
        int f = tid + i * 256;
        int row = f >> 3, c4 = f & 7;
        float4 v = *(const float4*)(A + (size_t)(base + row) * Kdim + k0 + c4 * 4);
        __half2 h0 = __floats2half2_rn(v.x, v.y);
        __half2 h1 = __floats2half2_rn(v.z, v.w);
        int phys = (c4 >> 1) ^ ((row >> 1) & 3);
        uint2 u = make_uint2(h2u(h0), h2u(h1));
        *(uint2*)(S + row * 32 + phys * 8 + (c4 & 1) * 4) = u;
    }
}
// Load one 128x32 fp16 tile -> fp16 smem (swizzled). 2 iters.
__device__ __forceinline__ void load_tile_f16(__half* S, const __half* A,
                                              int base, int Kdim, int k0, int tid) {
#pragma unroll
    for (int i = 0; i < 2; i++) {
        int f = tid + i * 256;
        int row = f >> 2, g = f & 3;
        uint4 v = *(const uint4*)(A + (size_t)(base + row) * Kdim + k0 + g * 8);
        int phys = g ^ ((row >> 1) & 3);
        *(uint4*)(S + row * 32 + phys * 8) = v;
    }
}

// Inner MMA block over one staged BK=32 tile pair.
__device__ __forceinline__ void gemm_mmas(float acc[4][4][4],
                                          unsigned asmb, unsigned bsmb,
                                          int wm, int wn, int mq, int mr) {
    const int q2 = mr >> 1;
#pragma unroll
    for (int kk = 0; kk < 2; kk++) {
        unsigned a[4][4], bfr[2][4];
#pragma unroll
        for (int mi = 0; mi < 4; mi++) {
            int row = wm * 64 + mi * 16 + (mq & 1) * 8 + mr;
            ldm_x4(a[mi], asmb + row * 64 + (((2 * kk + (mq >> 1)) ^ q2) << 4));
        }
#pragma unroll
        for (int np = 0; np < 2; np++) {
            int row = wn * 32 + np * 16 + (mq >> 1) * 8 + mr;
            ldm_x4(bfr[np], bsmb + row * 64 + (((2 * kk + (mq & 1)) ^ q2) << 4));
        }
#pragma unroll
        for (int mi = 0; mi < 4; mi++)
#pragma unroll
            for (int ni = 0; ni < 4; ni++)
                mma_f16(acc[mi][ni], a[mi], &bfr[ni >> 1][(ni & 1) * 2]);
    }
}

// ---------------------------------------------------------------------------
// Fused K/Q/V projection GEMM: z selects weight/output; output fp16.
// C[M,N] = x[M,K] @ W[N,K]^T  (k-proj additionally scaled by 0.125)
// ---------------------------------------------------------------------------
__global__ void __launch_bounds__(256, 2)
proj3(const float* __restrict__ x,
      const float* __restrict__ Wk, const float* __restrict__ Wq,
      const float* __restrict__ Wv,
      __half* __restrict__ gk, __half* __restrict__ gq, __half* __restrict__ gv) {
    __shared__ __half As[128 * 32];
    __shared__ __half Bs[128 * 32];

    const float* Bm;
    __half* C;
    float scale;
    if (blockIdx.z == 0)      { Bm = Wk; C = gk; scale = 0.125f; }
    else if (blockIdx.z == 1) { Bm = Wq; C = gq; scale = 1.f; }
    else                      { Bm = Wv; C = gv; scale = 1.f; }

    const int tid = threadIdx.x, lane = tid & 31, warp = tid >> 5;
    const int wm = warp >> 2, wn = warp & 3;
    const int m0 = blockIdx.x * 128, n0 = blockIdx.y * 128;
    const int mq = lane >> 3, mr = lane & 7;
    const int lr = lane >> 2, lc = lane & 3;

    float acc[4][4][4];
#pragma unroll
    for (int mi = 0; mi < 4; mi++)
#pragma unroll
        for (int ni = 0; ni < 4; ni++)
#pragma unroll
            for (int r = 0; r < 4; r++) acc[mi][ni][r] = 0.f;

    const unsigned asmb = (unsigned)__cvta_generic_to_shared(As);
    const unsigned bsmb = (unsigned)__cvta_generic_to_shared(Bs);

    for (int k0 = 0; k0 < En; k0 += 32) {
        load_tile_f32(As, x, m0, En, k0, tid);
        load_tile_f32(Bs, Bm, n0, En, k0, tid);
        __syncthreads();
        gemm_mmas(acc, asmb, bsmb, wm, wn, mq, mr);
        __syncthreads();
    }

#pragma unroll
    for (int mi = 0; mi < 4; mi++) {
        int r = m0 + wm * 64 + mi * 16 + lr;
#pragma unroll
        for (int ni = 0; ni < 4; ni++) {
            int cb = n0 + wn * 32 + ni * 8 + 2 * lc;
            *(__half2*)(C + (size_t)r * En + cb) =
                __floats2half2_rn(acc[mi][ni][0] * scale, acc[mi][ni][1] * scale);
            *(__half2*)(C + (size_t)(r + 8) * En + cb) =
                __floats2half2_rn(acc[mi][ni][2] * scale, acc[mi][ni][3] * scale);
        }
    }
}

// ---------------------------------------------------------------------------
// Output projection GEMM: fp16 A (attention result) x fp32 W^T + bias -> fp32
// ---------------------------------------------------------------------------
__global__ void __launch_bounds__(256, 2)
gemm_out(const __half* __restrict__ A, const float* __restrict__ Bm,
         const float* __restrict__ bias, float* __restrict__ C) {
    __shared__ __half As[128 * 32];
    __shared__ __half Bs[128 * 32];

    const int tid = threadIdx.x, lane = tid & 31, warp = tid >> 5;
    const int wm = warp >> 2, wn = warp & 3;
    const int m0 = blockIdx.x * 128, n0 = blockIdx.y * 128;
    const int mq = lane >> 3, mr = lane & 7;
    const int lr = lane >> 2, lc = lane & 3;

    float acc[4][4][4];
#pragma unroll
    for (int mi = 0; mi < 4; mi++)
#pragma unroll
        for (int ni = 0; ni < 4; ni++)
#pragma unroll
            for (int r = 0; r < 4; r++) acc[mi][ni][r] = 0.f;

    const unsigned asmb = (unsigned)__cvta_generic_to_shared(As);
    const unsigned bsmb = (unsigned)__cvta_generic_to_shared(Bs);

    for (int k0 = 0; k0 < En; k0 += 32) {
        load_tile_f16(As, A, m0, En, k0, tid);
        load_tile_f32(Bs, Bm, n0, En, k0, tid);
        __syncthreads();
        gemm_mmas(acc, asmb, bsmb, wm, wn, mq, mr);
        __syncthreads();
    }

#pragma unroll
    for (int mi = 0; mi < 4; mi++) {
        int r = m0 + wm * 64 + mi * 16 + lr;
#pragma unroll
        for (int ni = 0; ni < 4; ni++) {
            int cb = n0 + wn * 32 + ni * 8 + 2 * lc;
            float b0 = bias[cb], b1 = bias[cb + 1];
            C[(size_t)r * En + cb]           = acc[mi][ni][0] + b0;
            C[(size_t)r * En + cb + 1]       = acc[mi][ni][1] + b1;
            C[(size_t)(r + 8) * En + cb]     = acc[mi][ni][2] + b0;
            C[(size_t)(r + 8) * En + cb + 1] = acc[mi][ni][3] + b1;
        }
    }
}

// ---------------------------------------------------------------------------
// FP16 tensor-core flash attention (roles swapped: "query"=k-proj, "key"=q-proj)
// CTA: 128 t-rows x one (b,h). 8 warps x 16 rows. s tiled by 64, causal.
// smem rows = 64 halves = 128B = 8 x 16B groups; swizzle phys = g ^ (row&7).
// Q/K/P frags: ldmatrix.x4; V frags: ldmatrix.x4.trans. All conflict-free.
// ---------------------------------------------------------------------------
__global__ void __launch_bounds__(256, 2)
attn_h(const __half* __restrict__ Kp, const __half* __restrict__ Qp,
       const __half* __restrict__ Vp, __half* __restrict__ Out) {
    extern __shared__ __align__(16) __half smh[];
    __half* Qt = smh;             // [128][64]
    __half* Kt = Qt + 128 * 64;   // [64][64]
    __half* Vt = Kt + 64 * 64;    // [64][64]
    __half* Ps = Vt + 64 * 64;    // [128][64]

    const int tid  = threadIdx.x;
    const int lane = tid & 31;
    const int warp = tid >> 5;
    const int lr   = lane >> 2;
    const int lc   = lane & 3;
    const int mq   = lane >> 3;
    const int mr   = lane & 7;

    const int tb = (gridDim.x - 1) - blockIdx.x;   // heavy tiles first
    const int h  = blockIdx.y;
    const int b  = blockIdx.z;
    const int t0 = tb * 128;

    const __half* kbase = Kp + (size_t)b * Tn * En + h * HSn;  // attention "Q"
    const __half* qbase = Qp + (size_t)b * Tn * En + h * HSn;  // attention "K"
    const __half* vbase = Vp + (size_t)b * Tn * En + h * HSn;

    // Load Q tile (pre-scaled fp16) with swizzle
#pragma unroll
    for (int i = 0; i < 4; i++) {
        int f = tid + i * 256;                 // 0..1023
        int r = f >> 3, g = f & 7;
        uint4 v = *(const uint4*)(kbase + (size_t)(t0 + r) * En + g * 8);
        *(uint4*)(Qt + r * 64 + ((g ^ (r & 7)) << 3)) = v;
    }

    float o[8][4];
#pragma unroll
    for (int ni = 0; ni < 8; ni++)
#pragma unroll
        for (int r = 0; r < 4; r++) o[ni][r] = 0.f;
    float m0f = -INFINITY, m1f = -INFINITY, l0 = 0.f, l1 = 0.f;

    // ldmatrix per-lane base addresses
    const unsigned qsmb = (unsigned)__cvta_generic_to_shared(Qt) +
                          (warp * 16 + (mq & 1) * 8 + mr) * 128;
    const unsigned psmb = (unsigned)__cvta_generic_to_shared(Ps) +
                          (warp * 16 + (mq & 1) * 8 + mr) * 128;
    const unsigned krowb = (unsigned)__cvta_generic_to_shared(Kt) +
                           ((mq >> 1) * 8 + mr) * 128;
    const unsigned vrowb = (unsigned)__cvta_generic_to_shared(Vt) +
                           ((mq & 1) * 8 + mr) * 128;
    const int qsel = mq >> 1;   // k-half select for A frags (Q/P)
    const int ksel = mq & 1;    // k-half select for K B-frags
    const int vsel = mq >> 1;   // d-group select for V B-frags

    const int row0 = t0 + warp * 16 + lr;
    const int row1 = row0 + 8;
    const int nsb = 2 * tb + 2;

    for (int sb = 0; sb < nsb; sb++) {
        const int s0 = sb * 64;
        __syncthreads();   // prior-iter reads of Kt/Vt complete
#pragma unroll
        for (int i = 0; i < 2; i++) {
            int f = tid + i * 256;             // 0..511
            int r = f >> 3, g = f & 7;
            int so = ((g ^ (r & 7)) << 3);
            *(uint4*)(Kt + r * 64 + so) =
                *(const uint4*)(qbase + (size_t)(s0 + r) * En + g * 8);
            *(uint4*)(Vt + r * 64 + so) =
                *(const uint4*)(vbase + (size_t)(s0 + r) * En + g * 8);
        }
        __syncthreads();

        // ---- S = Q @ K^T ----
        float s[8][4];
#pragma unroll
        for (int ni = 0; ni < 8; ni++)
#pragma unroll
            for (int r = 0; r < 4; r++) s[ni][r] = 0.f;

#pragma unroll
        for (int kk = 0; kk < 4; kk++) {
            unsigned aq[4];
            ldm_x4(aq, qsmb + (((2 * kk + qsel) ^ mr) << 4));
#pragma unroll
            for (int np = 0; np < 4; np++) {
                unsigned kf[4];
                ldm_x4(kf, krowb + np * 2048 + (((2 * kk + ksel) ^ mr) << 4));
                mma_f16(s[2 * np],     aq, kf);
                mma_f16(s[2 * np + 1], aq, kf + 2);
            }
        }

        // ---- causal mask (only diagonal-adjacent s-blocks) ----
        if (s0 + 63 > t0) {
#pragma unroll
            for (int ni = 0; ni < 8; ni++) {
                int c0 = s0 + ni * 8 + 2 * lc;
                if (c0 > row0)     s[ni][0] = -INFINITY;
                if (c0 + 1 > row0) s[ni][1] = -INFINITY;
                if (c0 > row1)     s[ni][2] = -INFINITY;
                if (c0 + 1 > row1) s[ni][3] = -INFINITY;
            }
        }

        // ---- online softmax (rows within quad: shfl_xor 1,2) ----
        float rm0 = -INFINITY, rm1 = -INFINITY;
#pragma unroll
        for (int ni = 0; ni < 8; ni++) {
            rm0 = fmaxf(rm0, fmaxf(s[ni][0], s[ni][1]));
            rm1 = fmaxf(rm1, fmaxf(s[ni][2], s[ni][3]));
        }
        rm0 = fmaxf(rm0, __shfl_xor_sync(0xffffffffu, rm0, 1));
        rm0 = fmaxf(rm0, __shfl_xor_sync(0xffffffffu, rm0, 2));
        rm1 = fmaxf(rm1, __shfl_xor_sync(0xffffffffu, rm1, 1));
        rm1 = fmaxf(rm1, __shfl_xor_sync(0xffffffffu, rm1, 2));

        float mn0 = fmaxf(m0f, rm0);
        float mn1 = fmaxf(m1f, rm1);
        float corr0 = __expf(m0f - mn0);
        float corr1 = __expf(m1f - mn1);

        float rs0 = 0.f, rs1 = 0.f;
        __half* p0r = Ps + (warp * 16 + lr) * 64 + 2 * lc;
        __half* p1r = p0r + 8 * 64;
#pragma unroll
        for (int ni = 0; ni < 8; ni++) {
            float p0 = __expf(s[ni][0] - mn0);
            float p1 = __expf(s[ni][1] - mn0);
            float p2 = __expf(s[ni][2] - mn1);
            float p3 = __expf(s[ni][3] - mn1);
            rs0 += p0 + p1;
            rs1 += p2 + p3;
            int sw = (ni ^ lr) << 3;           // swizzled 8-half group offset
            *(__half2*)(p0r + sw) = __floats2half2_rn(p0, p1);
            *(__half2*)(p1r + sw) = __floats2half2_rn(p2, p3);
        }
        rs0 += __shfl_xor_sync(0xffffffffu, rs0, 1);
        rs0 += __shfl_xor_sync(0xffffffffu, rs0, 2);
        rs1 += __shfl_xor_sync(0xffffffffu, rs1, 1);
        rs1 += __shfl_xor_sync(0xffffffffu, rs1, 2);

        l0 = l0 * corr0 + rs0;
        l1 = l1 * corr1 + rs1;
        m0f = mn0;
        m1f = mn1;
#pragma unroll
        for (int ni = 0; ni < 8; ni++) {
            o[ni][0] *= corr0;
            o[ni][1] *= corr0;
            o[ni][2] *= corr1;
            o[ni][3] *= corr1;
        }
        __syncwarp();   // each warp reads back ONLY its own P rows

        // ---- O += P @ V ----
#pragma unroll
        for (int kk = 0; kk < 4; kk++) {
            unsigned ap[4];
            ldm_x4(ap, psmb + (((2 * kk + qsel) ^ mr) << 4));
#pragma unroll
            for (int np = 0; np < 4; np++) {
                unsigned vf[4];
                ldm_x4_t(vf, vrowb + kk * 2048 + (((2 * np + vsel) ^ mr) << 4));
                mma_f16(o[2 * np],     ap, vf);
                mma_f16(o[2 * np + 1], ap, vf + 2);
            }
        }
    }

    // ---- epilogue: normalize, fp16 store ----
    float inv0 = 1.f / l0;
    float inv1 = 1.f / l1;
    __half* ob = Out + (size_t)b * Tn * En + h * HSn;
#pragma unroll
    for (int ni = 0; ni < 8; ni++) {
        int c = ni * 8 + 2 * lc;
        *(__half2*)(ob + (size_t)row0 * En + c) =
            __floats2half2_rn(o[ni][0] * inv0, o[ni][1] * inv0);
        *(__half2*)(ob + (size_t)row1 * En + c) =
            __floats2half2_rn(o[ni][2] * inv1, o[ni][3] * inv1);
    }
}

// ---------------------------------------------------------------------------

static const int ATTN_SMEM = (128 + 64 + 64 + 128) * 64 * 2;  // 49152

extern "C" void kernel_launch(void* const* d_in, const int* in_sizes, int n_in,
                              void* d_out, int out_size) {
    (void)in_sizes; (void)n_in; (void)out_size;
    const float* x  = (const float*)d_in[0];
    const float* Wk = (const float*)d_in[1];
    const float* Wq = (const float*)d_in[2];
    const float* Wv = (const float*)d_in[3];
    const float* Wo = (const float*)d_in[4];
    const float* bo = (const float*)d_in[5];
    float* out = (float*)d_out;

    __half *gk, *gq, *gv, *ga;
    cudaGetSymbolAddress((void**)&gk, g_k);
    cudaGetSymbolAddress((void**)&gq, g_q);
    cudaGetSymbolAddress((void**)&gv, g_v);
    cudaGetSymbolAddress((void**)&ga, g_att);

    cudaFuncSetAttribute(attn_h,
                         cudaFuncAttributeMaxDynamicSharedMemorySize, ATTN_SMEM);

    dim3 gproj(Mn / 128, En / 128, 3);
    proj3<<<gproj, 256>>>(x, Wk, Wq, Wv, gk, gq, gv);

    dim3 gattn(Tn / 128, Hn, Bn);
    attn_h<<<gattn, 256, ATTN_SMEM>>>(gk, gq, gv, ga);

    dim3 gout(Mn / 128, En / 128);
    gemm_out<<<gout, 256>>>(ga, Wo, bo, out);
}

// round 8
// speedup vs baseline: 10.5651x; 1.3660x over previous
#include <cuda_runtime.h>
#include <cuda_fp16.h>
#include <math.h>

#define Bn 4
#define Tn 2048
#define En 1024
#define Hn 16
#define HSn 64
#define Mn (Bn * Tn)   // 8192

// Scratch buffers (device globals: allocation-free rule). fp16 everywhere.
__device__ __half g_xh[Mn * En];
__device__ __half g_wk[En * En];
__device__ __half g_wq[En * En];
__device__ __half g_wv[En * En];
__device__ __half g_wo[En * En];
__device__ __half g_k[Mn * En];
__device__ __half g_q[Mn * En];
__device__ __half g_v[Mn * En];
__device__ __half g_att[Mn * En];

__device__ __forceinline__ void mma_f16(float* c, const unsigned* a, const unsigned* b) {
    asm volatile(
        "mma.sync.aligned.m16n8k16.row.col.f32.f16.f16.f32 "
        "{%0,%1,%2,%3}, {%4,%5,%6,%7}, {%8,%9}, {%0,%1,%2,%3};"
        : "+f"(c[0]), "+f"(c[1]), "+f"(c[2]), "+f"(c[3])
        : "r"(a[0]), "r"(a[1]), "r"(a[2]), "r"(a[3]), "r"(b[0]), "r"(b[1]));
}
__device__ __forceinline__ void ldm_x4(unsigned* r, unsigned a) {
    asm volatile("ldmatrix.sync.aligned.m8n8.x4.shared.b16 {%0,%1,%2,%3}, [%4];"
                 : "=r"(r[0]), "=r"(r[1]), "=r"(r[2]), "=r"(r[3]) : "r"(a));
}
__device__ __forceinline__ void ldm_x4_t(unsigned* r, unsigned a) {
    asm volatile("ldmatrix.sync.aligned.m8n8.x4.trans.shared.b16 {%0,%1,%2,%3}, [%4];"
                 : "=r"(r[0]), "=r"(r[1]), "=r"(r[2]), "=r"(r[3]) : "r"(a));
}
__device__ __forceinline__ unsigned h2u(__half2 h) {
    return *reinterpret_cast<unsigned*>(&h);
}
__device__ __forceinline__ void cpa16(unsigned dst, const void* src) {
    asm volatile("cp.async.cg.shared.global [%0], [%1], 16;" :: "r"(dst), "l"(src));
}

// ---------------------------------------------------------------------------
// One-time fp32 -> fp16 conversion kernels
// ---------------------------------------------------------------------------
__global__ void cvt_x(const float* __restrict__ x, __half* __restrict__ xh) {
    size_t i = ((size_t)blockIdx.x * 256 + threadIdx.x) * 4;
    float4 v = *(const float4*)(x + i);
    *(uint2*)(xh + i) = make_uint2(h2u(__floats2half2_rn(v.x, v.y)),
                                   h2u(__floats2half2_rn(v.z, v.w)));
}
__global__ void cvt_w(const float* __restrict__ wk, const float* __restrict__ wq,
                      const float* __restrict__ wv, const float* __restrict__ wo,
                      __half* __restrict__ hk, __half* __restrict__ hq,
                      __half* __restrict__ hv, __half* __restrict__ ho) {
    const float* s;
    __half* d;
    float sc = 1.f;
    if (blockIdx.y == 0)      { s = wk; d = hk; sc = 0.125f; }  // exact pow2 fold
    else if (blockIdx.y == 1) { s = wq; d = hq; }
    else if (blockIdx.y == 2) { s = wv; d = hv; }
    else                      { s = wo; d = ho; }
    size_t i = ((size_t)blockIdx.x * 256 + threadIdx.x) * 4;
    float4 v = *(const float4*)(s + i);
    *(uint2*)(d + i) = make_uint2(h2u(__floats2half2_rn(v.x * sc, v.y * sc)),
                                  h2u(__floats2half2_rn(v.z * sc, v.w * sc)));
}

// ===========================================================================
// FP16 NT GEMM body: C[M,N] = A[M,K] @ Bm[N,K]^T, 128x128 tile, BK=64,
// 2-stage cp.async pipeline. smem row = 64 halves = 128B = 8 x 16B groups,
// swizzle phys = g ^ (row & 7) (same layout as attn, validated in R6).
// ===========================================================================
__device__ __forceinline__ void gemm_body(
    const __half* __restrict__ A, const __half* __restrict__ Bm,
    float acc[4][4][4], __half* sm, int m0, int n0) {
    const int tid = threadIdx.x, lane = tid & 31, warp = tid >> 5;
    const int wm = warp >> 2, wn = warp & 3;
    const int mq = lane >> 3, mr = lane & 7;
    const unsigned smb = (unsigned)__cvta_generic_to_shared(sm);

    // stage layout: [st][ A(8192h) | B(8192h) ], st stride 32768 bytes
#define LOAD_STAGE(st, k0)                                                     \
    {                                                                          \
        _Pragma("unroll")                                                      \
        for (int i = 0; i < 4; i++) {                                          \
            int f = tid + i * 256;                                             \
            int r = f >> 3, g = f & 7;                                         \
            unsigned off = (unsigned)((r * 64 + ((g ^ (r & 7)) << 3)) * 2);    \
            cpa16(smb + (st) * 32768 + off,                                    \
                  A + (size_t)(m0 + r) * En + (k0) + g * 8);                   \
            cpa16(smb + (st) * 32768 + 16384 + off,                            \
                  Bm + (size_t)(n0 + r) * En + (k0) + g * 8);                  \
        }                                                                      \
        asm volatile("cp.async.commit_group;");                                \
    }

    LOAD_STAGE(0, 0)
    for (int kt = 0; kt < 16; kt++) {
        if (kt + 1 < 16) {
            LOAD_STAGE((kt + 1) & 1, (kt + 1) * 64)
            asm volatile("cp.async.wait_group 1;");
        } else {
            asm volatile("cp.async.wait_group 0;");
        }
        __syncthreads();

        const unsigned asb = smb + (kt & 1) * 32768;
        const unsigned bsb = asb + 16384;
#pragma unroll
        for (int kk = 0; kk < 4; kk++) {
            unsigned a[4][4], bfr[2][4];
#pragma unroll
            for (int mi = 0; mi < 4; mi++) {
                int row = wm * 64 + mi * 16 + (mq & 1) * 8 + mr;
                ldm_x4(a[mi], asb + row * 128 + (((2 * kk + (mq >> 1)) ^ mr) << 4));
            }
#pragma unroll
            for (int np = 0; np < 2; np++) {
                int row = wn * 32 + np * 16 + (mq >> 1) * 8 + mr;
                ldm_x4(bfr[np], bsb + row * 128 + (((2 * kk + (mq & 1)) ^ mr) << 4));
            }
#pragma unroll
            for (int mi = 0; mi < 4; mi++)
#pragma unroll
                for (int ni = 0; ni < 4; ni++)
                    mma_f16(acc[mi][ni], a[mi], &bfr[ni >> 1][(ni & 1) * 2]);
        }
        __syncthreads();
    }
#undef LOAD_STAGE
}

static const int GEMM_SMEM = 65536;

// ---------------------------------------------------------------------------
// Fused K/Q/V projection (z selects weight/output); fp16 in, fp16 out.
// Wk is pre-scaled by 0.125 at conversion time.
// ---------------------------------------------------------------------------
__global__ void __launch_bounds__(256, 2)
proj3(const __half* __restrict__ xh,
      const __half* __restrict__ wk, const __half* __restrict__ wq,
      const __half* __restrict__ wv,
      __half* __restrict__ gk, __half* __restrict__ gq, __half* __restrict__ gv) {
    extern __shared__ __align__(16) __half smg[];
    const __half* Bm;
    __half* C;
    if (blockIdx.z == 0)      { Bm = wk; C = gk; }
    else if (blockIdx.z == 1) { Bm = wq; C = gq; }
    else                      { Bm = wv; C = gv; }

    float acc[4][4][4];
#pragma unroll
    for (int mi = 0; mi < 4; mi++)
#pragma unroll
        for (int ni = 0; ni < 4; ni++)
#pragma unroll
            for (int r = 0; r < 4; r++) acc[mi][ni][r] = 0.f;

    const int m0 = blockIdx.x * 128, n0 = blockIdx.y * 128;
    gemm_body(xh, Bm, acc, smg, m0, n0);

    const int lane = threadIdx.x & 31, warp = threadIdx.x >> 5;
    const int wm = warp >> 2, wn = warp & 3;
    const int lr = lane >> 2, lc = lane & 3;
#pragma unroll
    for (int mi = 0; mi < 4; mi++) {
        int r = m0 + wm * 64 + mi * 16 + lr;
#pragma unroll
        for (int ni = 0; ni < 4; ni++) {
            int cb = n0 + wn * 32 + ni * 8 + 2 * lc;
            *(__half2*)(C + (size_t)r * En + cb) =
                __floats2half2_rn(acc[mi][ni][0], acc[mi][ni][1]);
            *(__half2*)(C + (size_t)(r + 8) * En + cb) =
                __floats2half2_rn(acc[mi][ni][2], acc[mi][ni][3]);
        }
    }
}

// ---------------------------------------------------------------------------
// Output projection: fp16 A x fp16 W^T + fp32 bias -> fp32 out
// ---------------------------------------------------------------------------
__global__ void __launch_bounds__(256, 2)
gemm_out(const __half* __restrict__ A, const __half* __restrict__ Bm,
         const float* __restrict__ bias, float* __restrict__ C) {
    extern __shared__ __align__(16) __half smg[];
    float acc[4][4][4];
#pragma unroll
    for (int mi = 0; mi < 4; mi++)
#pragma unroll
        for (int ni = 0; ni < 4; ni++)
#pragma unroll
            for (int r = 0; r < 4; r++) acc[mi][ni][r] = 0.f;

    const int m0 = blockIdx.x * 128, n0 = blockIdx.y * 128;
    gemm_body(A, Bm, acc, smg, m0, n0);

    const int lane = threadIdx.x & 31, warp = threadIdx.x >> 5;
    const int wm = warp >> 2, wn = warp & 3;
    const int lr = lane >> 2, lc = lane & 3;
#pragma unroll
    for (int mi = 0; mi < 4; mi++) {
        int r = m0 + wm * 64 + mi * 16 + lr;
#pragma unroll
        for (int ni = 0; ni < 4; ni++) {
            int cb = n0 + wn * 32 + ni * 8 + 2 * lc;
            float b0 = bias[cb], b1 = bias[cb + 1];
            C[(size_t)r * En + cb]           = acc[mi][ni][0] + b0;
            C[(size_t)r * En + cb + 1]       = acc[mi][ni][1] + b1;
            C[(size_t)(r + 8) * En + cb]     = acc[mi][ni][2] + b0;
            C[(size_t)(r + 8) * En + cb + 1] = acc[mi][ni][3] + b1;
        }
    }
}

// ---------------------------------------------------------------------------
// FP16 flash attention with 2-stage cp.async K/V prefetch.
// CTA: 128 t-rows x one (b,h). 8 warps x 16 rows. s tiled by 64, causal.
// smem: Qt 16KB | Ps 16KB | KV[2 stages][K 8KB | V 8KB] = 64KB.
// ---------------------------------------------------------------------------
__global__ void __launch_bounds__(256, 2)
attn_h(const __half* __restrict__ Kp, const __half* __restrict__ Qp,
       const __half* __restrict__ Vp, __half* __restrict__ Out) {
    extern __shared__ __align__(16) __half smh[];
    __half* Qt  = smh;              // [128][64]
    __half* Ps  = Qt + 128 * 64;    // [128][64]
    __half* KVs = Ps + 128 * 64;    // [2][K 64x64 | V 64x64]

    const int tid  = threadIdx.x;
    const int lane = tid & 31;
    const int warp = tid >> 5;
    const int lr   = lane >> 2;
    const int lc   = lane & 3;
    const int mq   = lane >> 3;
    const int mr   = lane & 7;

    const int tb = (gridDim.x - 1) - blockIdx.x;   // heavy tiles first
    const int h  = blockIdx.y;
    const int b  = blockIdx.z;
    const int t0 = tb * 128;

    const __half* kbase = Kp + (size_t)b * Tn * En + h * HSn;  // attention "Q"
    const __half* qbase = Qp + (size_t)b * Tn * En + h * HSn;  // attention "K"
    const __half* vbase = Vp + (size_t)b * Tn * En + h * HSn;

    const unsigned kvsmb = (unsigned)__cvta_generic_to_shared(KVs);

#define KV_PREFETCH(st, s0)                                                    \
    {                                                                          \
        _Pragma("unroll")                                                      \
        for (int i = 0; i < 2; i++) {                                          \
            int f = tid + i * 256;                                             \
            int r = f >> 3, g = f & 7;                                         \
            unsigned off = (unsigned)((r * 64 + ((g ^ (r & 7)) << 3)) * 2);    \
            cpa16(kvsmb + (st) * 16384 + off,                                  \
                  qbase + (size_t)((s0) + r) * En + g * 8);                    \
            cpa16(kvsmb + (st) * 16384 + 8192 + off,                           \
                  vbase + (size_t)((s0) + r) * En + g * 8);                    \
        }                                                                      \
        asm volatile("cp.async.commit_group;");                                \
    }

    KV_PREFETCH(0, 0)

    // Load Q tile (pre-scaled fp16) with swizzle
#pragma unroll
    for (int i = 0; i < 4; i++) {
        int f = tid + i * 256;
        int r = f >> 3, g = f & 7;
        uint4 v = *(const uint4*)(kbase + (size_t)(t0 + r) * En + g * 8);
        *(uint4*)(Qt + r * 64 + ((g ^ (r & 7)) << 3)) = v;
    }

    float o[8][4];
#pragma unroll
    for (int ni = 0; ni < 8; ni++)
#pragma unroll
        for (int r = 0; r < 4; r++) o[ni][r] = 0.f;
    float m0f = -INFINITY, m1f = -INFINITY, l0 = 0.f, l1 = 0.f;

    const unsigned qsmb = (unsigned)__cvta_generic_to_shared(Qt) +
                          (warp * 16 + (mq & 1) * 8 + mr) * 128;
    const unsigned psmb = (unsigned)__cvta_generic_to_shared(Ps) +
                          (warp * 16 + (mq & 1) * 8 + mr) * 128;
    const unsigned krowo = ((mq >> 1) * 8 + mr) * 128;       // within K stage
    const unsigned vrowo = 8192 + ((mq & 1) * 8 + mr) * 128; // within stage (V)
    const int qsel = mq >> 1;
    const int ksel = mq & 1;
    const int vsel = mq >> 1;

    const int row0 = t0 + warp * 16 + lr;
    const int row1 = row0 + 8;
    const int nsb = 2 * tb + 2;

    for (int sb = 0; sb < nsb; sb++) {
        const int s0 = sb * 64;
        if (sb + 1 < nsb) {
            KV_PREFETCH((sb + 1) & 1, s0 + 64)
            asm volatile("cp.async.wait_group 1;");
        } else {
            asm volatile("cp.async.wait_group 0;");
        }
        __syncthreads();

        const unsigned kst = kvsmb + (sb & 1) * 16384 + krowo;
        const unsigned vst = kvsmb + (sb & 1) * 16384 + vrowo;

        // ---- S = Q @ K^T ----
        float s[8][4];
#pragma unroll
        for (int ni = 0; ni < 8; ni++)
#pragma unroll
            for (int r = 0; r < 4; r++) s[ni][r] = 0.f;

#pragma unroll
        for (int kk = 0; kk < 4; kk++) {
            unsigned aq[4];
            ldm_x4(aq, qsmb + (((2 * kk + qsel) ^ mr) << 4));
#pragma unroll
            for (int np = 0; np < 4; np++) {
                unsigned kf[4];
                ldm_x4(kf, kst + np * 2048 + (((2 * kk + ksel) ^ mr) << 4));
                mma_f16(s[2 * np],     aq, kf);
                mma_f16(s[2 * np + 1], aq, kf + 2);
            }
        }

        // ---- causal mask (only diagonal-adjacent s-blocks) ----
        if (s0 + 63 > t0) {
#pragma unroll
            for (int ni = 0; ni < 8; ni++) {
                int c0 = s0 + ni * 8 + 2 * lc;
                if (c0 > row0)     s[ni][0] = -INFINITY;
                if (c0 + 1 > row0) s[ni][1] = -INFINITY;
                if (c0 > row1)     s[ni][2] = -INFINITY;
                if (c0 + 1 > row1) s[ni][3] = -INFINITY;
            }
        }

        // ---- online softmax (rows within quad: shfl_xor 1,2) ----
        float rm0 = -INFINITY, rm1 = -INFINITY;
#pragma unroll
        for (int ni = 0; ni < 8; ni++) {
            rm0 = fmaxf(rm0, fmaxf(s[ni][0], s[ni][1]));
            rm1 = fmaxf(rm1, fmaxf(s[ni][2], s[ni][3]));
        }
        rm0 = fmaxf(rm0, __shfl_xor_sync(0xffffffffu, rm0, 1));
        rm0 = fmaxf(rm0, __shfl_xor_sync(0xffffffffu, rm0, 2));
        rm1 = fmaxf(rm1, __shfl_xor_sync(0xffffffffu, rm1, 1));
        rm1 = fmaxf(rm1, __shfl_xor_sync(0xffffffffu, rm1, 2));

        float mn0 = fmaxf(m0f, rm0);
        float mn1 = fmaxf(m1f, rm1);
        float corr0 = __expf(m0f - mn0);
        float corr1 = __expf(m1f - mn1);

        float rs0 = 0.f, rs1 = 0.f;
        __half* p0r = Ps + (warp * 16 + lr) * 64 + 2 * lc;
        __half* p1r = p0r + 8 * 64;
#pragma unroll
        for (int ni = 0; ni < 8; ni++) {
            float p0 = __expf(s[ni][0] - mn0);
            float p1 = __expf(s[ni][1] - mn0);
            float p2 = __expf(s[ni][2] - mn1);
            float p3 = __expf(s[ni][3] - mn1);
            rs0 += p0 + p1;
            rs1 += p2 + p3;
            int sw = (ni ^ lr) << 3;
            *(__half2*)(p0r + sw) = __floats2half2_rn(p0, p1);
            *(__half2*)(p1r + sw) = __floats2half2_rn(p2, p3);
        }
        rs0 += __shfl_xor_sync(0xffffffffu, rs0, 1);
        rs0 += __shfl_xor_sync(0xffffffffu, rs0, 2);
        rs1 += __shfl_xor_sync(0xffffffffu, rs1, 1);
        rs1 += __shfl_xor_sync(0xffffffffu, rs1, 2);

        l0 = l0 * corr0 + rs0;
        l1 = l1 * corr1 + rs1;
        m0f = mn0;
        m1f = mn1;
#pragma unroll
        for (int ni = 0; ni < 8; ni++) {
            o[ni][0] *= corr0;
            o[ni][1] *= corr0;
            o[ni][2] *= corr1;
            o[ni][3] *= corr1;
        }
        __syncwarp();   // each warp reads back ONLY its own P rows

        // ---- O += P @ V ----
#pragma unroll
        for (int kk = 0; kk < 4; kk++) {
            unsigned ap[4];
            ldm_x4(ap, psmb + (((2 * kk + qsel) ^ mr) << 4));
#pragma unroll
            for (int np = 0; np < 4; np++) {
                unsigned vf[4];
                ldm_x4_t(vf, vst + kk * 2048 + (((2 * np + vsel) ^ mr) << 4));
                mma_f16(o[2 * np],     ap, vf);
                mma_f16(o[2 * np + 1], ap, vf + 2);
            }
        }
        __syncthreads();   // all warps done with this stage before overwrite
    }
#undef KV_PREFETCH

    // ---- epilogue: normalize, fp16 store ----
    float inv0 = 1.f / l0;
    float inv1 = 1.f / l1;
    __half* ob = Out + (size_t)b * Tn * En + h * HSn;
#pragma unroll
    for (int ni = 0; ni < 8; ni++) {
        int c = ni * 8 + 2 * lc;
        *(__half2*)(ob + (size_t)row0 * En + c) =
            __floats2half2_rn(o[ni][0] * inv0, o[ni][1] * inv0);
        *(__half2*)(ob + (size_t)row1 * En + c) =
            __floats2half2_rn(o[ni][2] * inv1, o[ni][3] * inv1);
    }
}

static const int ATTN_SMEM = (128 * 64 + 128 * 64 + 2 * 2 * 64 * 64) * 2;  // 65536

// ---------------------------------------------------------------------------

extern "C" void kernel_launch(void* const* d_in, const int* in_sizes, int n_in,
                              void* d_out, int out_size) {
    (void)in_sizes; (void)n_in; (void)out_size;
    const float* x  = (const float*)d_in[0];
    const float* Wk = (const float*)d_in[1];
    const float* Wq = (const float*)d_in[2];
    const float* Wv = (const float*)d_in[3];
    const float* Wo = (const float*)d_in[4];
    const float* bo = (const float*)d_in[5];
    float* out = (float*)d_out;

    __half *xh, *wk, *wq, *wv, *wo, *gk, *gq, *gv, *ga;
    cudaGetSymbolAddress((void**)&xh, g_xh);
    cudaGetSymbolAddress((void**)&wk, g_wk);
    cudaGetSymbolAddress((void**)&wq, g_wq);
    cudaGetSymbolAddress((void**)&wv, g_wv);
    cudaGetSymbolAddress((void**)&wo, g_wo);
    cudaGetSymbolAddress((void**)&gk, g_k);
    cudaGetSymbolAddress((void**)&gq, g_q);
    cudaGetSymbolAddress((void**)&gv, g_v);
    cudaGetSymbolAddress((void**)&ga, g_att);

    cudaFuncSetAttribute(attn_h, cudaFuncAttributeMaxDynamicSharedMemorySize, ATTN_SMEM);
    cudaFuncSetAttribute(proj3, cudaFuncAttributeMaxDynamicSharedMemorySize, GEMM_SMEM);
    cudaFuncSetAttribute(gemm_out, cudaFuncAttributeMaxDynamicSharedMemorySize, GEMM_SMEM);

    cvt_x<<<Mn * En / 1024, 256>>>(x, xh);
    cvt_w<<<dim3(En * En / 1024, 4), 256>>>(Wk, Wq, Wv, Wo, wk, wq, wv, wo);

    dim3 gproj(Mn / 128, En / 128, 3);
    proj3<<<gproj, 256, GEMM_SMEM>>>(xh, wk, wq, wv, gk, gq, gv);

    dim3 gattn(Tn / 128, Hn, Bn);
    attn_h<<<gattn, 256, ATTN_SMEM>>>(gk, gq, gv, ga);

    dim3 gout(Mn / 128, En / 128);
    gemm_out<<<gout, 256, GEMM_SMEM>>>(ga, wo, bo, out);
}

// round 11
// speedup vs baseline: 11.0067x; 1.0418x over previous
#include <cuda_runtime.h>
#include <cuda_fp16.h>
#include <cstdint>
#include <math.h>

#define Bn 4
#define Tn 2048
#define En 1024
#define Hn 16
#define HSn 64
#define Mn (Bn * Tn)   // 8192

// Scratch buffers (device globals: allocation-free rule). fp16 everywhere.
__device__ __half g_xh[Mn * En];
__device__ __half g_wk[En * En];
__device__ __half g_wq[En * En];
__device__ __half g_wv[En * En];
__device__ __half g_wo[En * En];
__device__ __half g_k[Mn * En];
__device__ __half g_q[Mn * En];
__device__ __half g_v[Mn * En];
__device__ __half g_att[Mn * En];

__device__ __forceinline__ void mma_f16(float* c, const unsigned* a, const unsigned* b) {
    asm volatile(
        "mma.sync.aligned.m16n8k16.row.col.f32.f16.f16.f32 "
        "{%0,%1,%2,%3}, {%4,%5,%6,%7}, {%8,%9}, {%0,%1,%2,%3};"
        : "+f"(c[0]), "+f"(c[1]), "+f"(c[2]), "+f"(c[3])
        : "r"(a[0]), "r"(a[1]), "r"(a[2]), "r"(a[3]), "r"(b[0]), "r"(b[1]));
}
__device__ __forceinline__ void ldm_x4(unsigned* r, unsigned a) {
    asm volatile("ldmatrix.sync.aligned.m8n8.x4.shared.b16 {%0,%1,%2,%3}, [%4];"
                 : "=r"(r[0]), "=r"(r[1]), "=r"(r[2]), "=r"(r[3]) : "r"(a));
}
__device__ __forceinline__ void ldm_x4_t(unsigned* r, unsigned a) {
    asm volatile("ldmatrix.sync.aligned.m8n8.x4.trans.shared.b16 {%0,%1,%2,%3}, [%4];"
                 : "=r"(r[0]), "=r"(r[1]), "=r"(r[2]), "=r"(r[3]) : "r"(a));
}
__device__ __forceinline__ unsigned h2u(__half2 h) {
    return *reinterpret_cast<unsigned*>(&h);
}
__device__ __forceinline__ void cpa16(unsigned dst, const void* src) {
    asm volatile("cp.async.cg.shared.global [%0], [%1], 16;" :: "r"(dst), "l"(src));
}

// ---------------------------------------------------------------------------
// One-time fp32 -> fp16 conversion kernels
// ---------------------------------------------------------------------------
__global__ void cvt_x(const float* __restrict__ x, __half* __restrict__ xh) {
    size_t i = ((size_t)blockIdx.x * 256 + threadIdx.x) * 4;
    float4 v = *(const float4*)(x + i);
    *(uint2*)(xh + i) = make_uint2(h2u(__floats2half2_rn(v.x, v.y)),
                                   h2u(__floats2half2_rn(v.z, v.w)));
}
__global__ void cvt_w(const float* __restrict__ wk, const float* __restrict__ wq,
                      const float* __restrict__ wv, const float* __restrict__ wo,
                      __half* __restrict__ hk, __half* __restrict__ hq,
                      __half* __restrict__ hv, __half* __restrict__ ho) {
    const float* s;
    __half* d;
    float sc = 1.f;
    if (blockIdx.y == 0)      { s = wk; d = hk; sc = 0.125f; }  // exact pow2 fold
    else if (blockIdx.y == 1) { s = wq; d = hq; }
    else if (blockIdx.y == 2) { s = wv; d = hv; }
    else                      { s = wo; d = ho; }
    size_t i = ((size_t)blockIdx.x * 256 + threadIdx.x) * 4;
    float4 v = *(const float4*)(s + i);
    *(uint2*)(d + i) = make_uint2(h2u(__floats2half2_rn(v.x * sc, v.y * sc)),
                                  h2u(__floats2half2_rn(v.z * sc, v.w * sc)));
}

// ===========================================================================
// FP16 NT GEMM body: C[M,N] = A[M,K] @ Bm[N,K]^T, 128x128 tile, BK=64,
// 2-stage cp.async pipeline. smem row = 64 halves = 128B = 8 x 16B groups,
// swizzle phys = g ^ (row & 7).  (R8-proven config.)
// ===========================================================================
__device__ __forceinline__ void gemm_body(
    const __half* __restrict__ A, const __half* __restrict__ Bm,
    float acc[4][4][4], __half* sm, int m0, int n0) {
    const int tid = threadIdx.x, lane = tid & 31, warp = tid >> 5;
    const int wm = warp >> 2, wn = warp & 3;
    const int mq = lane >> 3, mr = lane & 7;
    const unsigned smb = (unsigned)__cvta_generic_to_shared(sm);

#define LOAD_STAGE(st, k0)                                                     \
    {                                                                          \
        _Pragma("unroll")                                                      \
        for (int i = 0; i < 4; i++) {                                          \
            int f = tid + i * 256;                                             \
            int r = f >> 3, g = f & 7;                                         \
            unsigned off = (unsigned)((r * 64 + ((g ^ (r & 7)) << 3)) * 2);    \
            cpa16(smb + (st) * 32768 + off,                                    \
                  A + (size_t)(m0 + r) * En + (k0) + g * 8);                   \
            cpa16(smb + (st) * 32768 + 16384 + off,                            \
                  Bm + (size_t)(n0 + r) * En + (k0) + g * 8);                  \
        }                                                                      \
        asm volatile("cp.async.commit_group;");                                \
    }

    LOAD_STAGE(0, 0)
    for (int kt = 0; kt < 16; kt++) {
        if (kt + 1 < 16) {
            LOAD_STAGE((kt + 1) & 1, (kt + 1) * 64)
            asm volatile("cp.async.wait_group 1;");
        } else {
            asm volatile("cp.async.wait_group 0;");
        }
        __syncthreads();

        const unsigned asb = smb + (kt & 1) * 32768;
        const unsigned bsb = asb + 16384;
#pragma unroll
        for (int kk = 0; kk < 4; kk++) {
            unsigned a[4][4], bfr[2][4];
#pragma unroll
            for (int mi = 0; mi < 4; mi++) {
                int row = wm * 64 + mi * 16 + (mq & 1) * 8 + mr;
                ldm_x4(a[mi], asb + row * 128 + (((2 * kk + (mq >> 1)) ^ mr) << 4));
            }
#pragma unroll
            for (int np = 0; np < 2; np++) {
                int row = wn * 32 + np * 16 + (mq >> 1) * 8 + mr;
                ldm_x4(bfr[np], bsb + row * 128 + (((2 * kk + (mq & 1)) ^ mr) << 4));
            }
#pragma unroll
            for (int mi = 0; mi < 4; mi++)
#pragma unroll
                for (int ni = 0; ni < 4; ni++)
                    mma_f16(acc[mi][ni], a[mi], &bfr[ni >> 1][(ni & 1) * 2]);
        }
        __syncthreads();
    }
#undef LOAD_STAGE
}

static const int GEMM_SMEM = 65536;

// ---------------------------------------------------------------------------
// Fused K/Q/V projection (z selects weight/output); fp16 in, fp16 out.
// ---------------------------------------------------------------------------
__global__ void __launch_bounds__(256, 2)
proj3(const __half* __restrict__ xh,
      const __half* __restrict__ wk, const __half* __restrict__ wq,
      const __half* __restrict__ wv,
      __half* __restrict__ gk, __half* __restrict__ gq, __half* __restrict__ gv) {
    extern __shared__ __align__(16) __half smg[];
    const __half* Bm;
    __half* C;
    if (blockIdx.z == 0)      { Bm = wk; C = gk; }
    else if (blockIdx.z == 1) { Bm = wq; C = gq; }
    else                      { Bm = wv; C = gv; }

    float acc[4][4][4];
#pragma unroll
    for (int mi = 0; mi < 4; mi++)
#pragma unroll
        for (int ni = 0; ni < 4; ni++)
#pragma unroll
            for (int r = 0; r < 4; r++) acc[mi][ni][r] = 0.f;

    const int m0 = blockIdx.x * 128, n0 = blockIdx.y * 128;
    gemm_body(xh, Bm, acc, smg, m0, n0);

    const int lane = threadIdx.x & 31, warp = threadIdx.x >> 5;
    const int wm = warp >> 2, wn = warp & 3;
    const int lr = lane >> 2, lc = lane & 3;
#pragma unroll
    for (int mi = 0; mi < 4; mi++) {
        int r = m0 + wm * 64 + mi * 16 + lr;
#pragma unroll
        for (int ni = 0; ni < 4; ni++) {
            int cb = n0 + wn * 32 + ni * 8 + 2 * lc;
            *(__half2*)(C + (size_t)r * En + cb) =
                __floats2half2_rn(acc[mi][ni][0], acc[mi][ni][1]);
            *(__half2*)(C + (size_t)(r + 8) * En + cb) =
                __floats2half2_rn(acc[mi][ni][2], acc[mi][ni][3]);
        }
    }
}

// ---------------------------------------------------------------------------
// Output projection: fp16 A x fp16 W^T + fp32 bias -> fp32 out
// ---------------------------------------------------------------------------
__global__ void __launch_bounds__(256, 2)
gemm_out(const __half* __restrict__ A, const __half* __restrict__ Bm,
         const float* __restrict__ bias, float* __restrict__ C) {
    extern __shared__ __align__(16) __half smg[];
    float acc[4][4][4];
#pragma unroll
    for (int mi = 0; mi < 4; mi++)
#pragma unroll
        for (int ni = 0; ni < 4; ni++)
#pragma unroll
            for (int r = 0; r < 4; r++) acc[mi][ni][r] = 0.f;

    const int m0 = blockIdx.x * 128, n0 = blockIdx.y * 128;
    gemm_body(A, Bm, acc, smg, m0, n0);

    const int lane = threadIdx.x & 31, warp = threadIdx.x >> 5;
    const int wm = warp >> 2, wn = warp & 3;
    const int lr = lane >> 2, lc = lane & 3;
#pragma unroll
    for (int mi = 0; mi < 4; mi++) {
        int r = m0 + wm * 64 + mi * 16 + lr;
#pragma unroll
        for (int ni = 0; ni < 4; ni++) {
            int cb = n0 + wn * 32 + ni * 8 + 2 * lc;
            float b0 = bias[cb], b1 = bias[cb + 1];
            C[(size_t)r * En + cb]           = acc[mi][ni][0] + b0;
            C[(size_t)r * En + cb + 1]       = acc[mi][ni][1] + b1;
            C[(size_t)(r + 8) * En + cb]     = acc[mi][ni][2] + b0;
            C[(size_t)(r + 8) * En + cb + 1] = acc[mi][ni][3] + b1;
        }
    }
}

// ---------------------------------------------------------------------------
// FP16 flash attention, register-direct P (no smem roundtrip), Q frags hoisted.
// CTA: 128 t-rows x one (b,h). 8 warps x 16 rows. s tiled by 64, causal.
// smem: Qt 16KB | KV[2 stages][K 8KB | V 8KB] = 48KB.
// ---------------------------------------------------------------------------
__global__ void __launch_bounds__(256, 2)
attn_h(const __half* __restrict__ Kp, const __half* __restrict__ Qp,
       const __half* __restrict__ Vp, __half* __restrict__ Out) {
    extern __shared__ __align__(16) __half smh[];
    __half* Qt  = smh;              // [128][64]
    __half* KVs = Qt + 128 * 64;    // [2][K 64x64 | V 64x64]

    const int tid  = threadIdx.x;
    const int lane = tid & 31;
    const int warp = tid >> 5;
    const int lr   = lane >> 2;
    const int lc   = lane & 3;
    const int mq   = lane >> 3;
    const int mr   = lane & 7;

    const int tb = (gridDim.x - 1) - blockIdx.x;   // heavy tiles first
    const int h  = blockIdx.y;
    const int b  = blockIdx.z;
    const int t0 = tb * 128;

    const __half* kbase = Kp + (size_t)b * Tn * En + h * HSn;  // attention "Q"
    const __half* qbase = Qp + (size_t)b * Tn * En + h * HSn;  // attention "K"
    const __half* vbase = Vp + (size_t)b * Tn * En + h * HSn;

    const unsigned kvsmb = (unsigned)__cvta_generic_to_shared(KVs);

#define KV_PREFETCH(st, s0)                                                    \
    {                                                                          \
        _Pragma("unroll")                                                      \
        for (int i = 0; i < 2; i++) {                                          \
            int f = tid + i * 256;                                             \
            int r = f >> 3, g = f & 7;                                         \
            unsigned off = (unsigned)((r * 64 + ((g ^ (r & 7)) << 3)) * 2);    \
            cpa16(kvsmb + (st) * 16384 + off,                                  \
                  qbase + (size_t)((s0) + r) * En + g * 8);                    \
            cpa16(kvsmb + (st) * 16384 + 8192 + off,                           \
                  vbase + (size_t)((s0) + r) * En + g * 8);                    \
        }                                                                      \
        asm volatile("cp.async.commit_group;");                                \
    }

    KV_PREFETCH(0, 0)

    // Load Q tile (pre-scaled fp16) with swizzle, then hoist frags to registers
#pragma unroll
    for (int i = 0; i < 4; i++) {
        int f = tid + i * 256;
        int r = f >> 3, g = f & 7;
        uint4 v = *(const uint4*)(kbase + (size_t)(t0 + r) * En + g * 8);
        *(uint4*)(Qt + r * 64 + ((g ^ (r & 7)) << 3)) = v;
    }
    __syncthreads();

    const unsigned qsmb = (unsigned)__cvta_generic_to_shared(Qt) +
                          (warp * 16 + (mq & 1) * 8 + mr) * 128;
    const int qsel = mq >> 1;   // k-half select for Q A-frags
    const int ksel = mq & 1;    // k-half select for K B-frags
    const int vsel = mq >> 1;   // d-group select for V B-frags

    unsigned aq[4][4];          // Q fragments: invariant across s-blocks
#pragma unroll
    for (int kk = 0; kk < 4; kk++)
        ldm_x4(aq[kk], qsmb + (((2 * kk + qsel) ^ mr) << 4));

    float o[8][4];
#pragma unroll
    for (int ni = 0; ni < 8; ni++)
#pragma unroll
        for (int r = 0; r < 4; r++) o[ni][r] = 0.f;
    float m0f = -INFINITY, m1f = -INFINITY, l0 = 0.f, l1 = 0.f;

    const unsigned krowo = ((mq >> 1) * 8 + mr) * 128;       // within K stage
    const unsigned vrowo = 8192 + ((mq & 1) * 8 + mr) * 128; // within stage (V)

    const int row0 = t0 + warp * 16 + lr;
    const int row1 = row0 + 8;
    const int nsb = 2 * tb + 2;

    for (int sb = 0; sb < nsb; sb++) {
        const int s0 = sb * 64;
        if (sb + 1 < nsb) {
            KV_PREFETCH((sb + 1) & 1, s0 + 64)
            asm volatile("cp.async.wait_group 1;");
        } else {
            asm volatile("cp.async.wait_group 0;");
        }
        __syncthreads();

        const unsigned kst = kvsmb + (sb & 1) * 16384 + krowo;
        const unsigned vst = kvsmb + (sb & 1) * 16384 + vrowo;

        // ---- S = Q @ K^T ----
        float s[8][4];
#pragma unroll
        for (int ni = 0; ni < 8; ni++)
#pragma unroll
            for (int r = 0; r < 4; r++) s[ni][r] = 0.f;

#pragma unroll
        for (int kk = 0; kk < 4; kk++) {
#pragma unroll
            for (int np = 0; np < 4; np++) {
                unsigned kf[4];
                ldm_x4(kf, kst + np * 2048 + (((2 * kk + ksel) ^ mr) << 4));
                mma_f16(s[2 * np],     aq[kk], kf);
                mma_f16(s[2 * np + 1], aq[kk], kf + 2);
            }
        }

        // ---- causal mask (only diagonal-adjacent s-blocks) ----
        if (s0 + 63 > t0) {
#pragma unroll
            for (int ni = 0; ni < 8; ni++) {
                int c0 = s0 + ni * 8 + 2 * lc;
                if (c0 > row0)     s[ni][0] = -INFINITY;
                if (c0 + 1 > row0) s[ni][1] = -INFINITY;
                if (c0 > row1)     s[ni][2] = -INFINITY;
                if (c0 + 1 > row1) s[ni][3] = -INFINITY;
            }
        }

        // ---- online softmax (rows within quad: shfl_xor 1,2) ----
        float rm0 = -INFINITY, rm1 = -INFINITY;
#pragma unroll
        for (int ni = 0; ni < 8; ni++) {
            rm0 = fmaxf(rm0, fmaxf(s[ni][0], s[ni][1]));
            rm1 = fmaxf(rm1, fmaxf(s[ni][2], s[ni][3]));
        }
        rm0 = fmaxf(rm0, __shfl_xor_sync(0xffffffffu, rm0, 1));
        rm0 = fmaxf(rm0, __shfl_xor_sync(0xffffffffu, rm0, 2));
        rm1 = fmaxf(rm1, __shfl_xor_sync(0xffffffffu, rm1, 1));
        rm1 = fmaxf(rm1, __shfl_xor_sync(0xffffffffu, rm1, 2));

        float mn0 = fmaxf(m0f, rm0);
        float mn1 = fmaxf(m1f, rm1);
        float corr0 = __expf(m0f - mn0);
        float corr1 = __expf(m1f - mn1);

        // P stays in registers: C-frag of S == A-frag of P (fp16 m16n8k16)
        unsigned ph[8][2];
        float rs0 = 0.f, rs1 = 0.f;
#pragma unroll
        for (int ni = 0; ni < 8; ni++) {
            float p0 = __expf(s[ni][0] - mn0);
            float p1 = __expf(s[ni][1] - mn0);
            float p2 = __expf(s[ni][2] - mn1);
            float p3 = __expf(s[ni][3] - mn1);
            rs0 += p0 + p1;
            rs1 += p2 + p3;
            ph[ni][0] = h2u(__floats2half2_rn(p0, p1));   // row lr
            ph[ni][1] = h2u(__floats2half2_rn(p2, p3));   // row lr+8
        }
        rs0 += __shfl_xor_sync(0xffffffffu, rs0, 1);
        rs0 += __shfl_xor_sync(0xffffffffu, rs0, 2);
        rs1 += __shfl_xor_sync(0xffffffffu, rs1, 1);
        rs1 += __shfl_xor_sync(0xffffffffu, rs1, 2);

        l0 = l0 * corr0 + rs0;
        l1 = l1 * corr1 + rs1;
        m0f = mn0;
        m1f = mn1;
#pragma unroll
        for (int ni = 0; ni < 8; ni++) {
            o[ni][0] *= corr0;
            o[ni][1] *= corr0;
            o[ni][2] *= corr1;
            o[ni][3] *= corr1;
        }

        // ---- O += P @ V (A-frags straight from registers) ----
#pragma unroll
        for (int kk = 0; kk < 4; kk++) {
            unsigned ap[4] = { ph[2 * kk][0], ph[2 * kk][1],
                               ph[2 * kk + 1][0], ph[2 * kk + 1][1] };
#pragma unroll
            for (int np = 0; np < 4; np++) {
                unsigned vf[4];
                ldm_x4_t(vf, vst + kk * 2048 + (((2 * np + vsel) ^ mr) << 4));
                mma_f16(o[2 * np],     ap, vf);
                mma_f16(o[2 * np + 1], ap, vf + 2);
            }
        }
        __syncthreads();   // all warps done with this stage before overwrite
    }
#undef KV_PREFETCH

    // ---- epilogue: normalize, fp16 store ----
    float inv0 = 1.f / l0;
    float inv1 = 1.f / l1;
    __half* ob = Out + (size_t)b * Tn * En + h * HSn;
#pragma unroll
    for (int ni = 0; ni < 8; ni++) {
        int c = ni * 8 + 2 * lc;
        *(__half2*)(ob + (size_t)row0 * En + c) =
            __floats2half2_rn(o[ni][0] * inv0, o[ni][1] * inv0);
        *(__half2*)(ob + (size_t)row1 * En + c) =
            __floats2half2_rn(o[ni][2] * inv1, o[ni][3] * inv1);
    }
}

static const int ATTN_SMEM = (128 * 64 + 2 * 2 * 64 * 64) * 2;  // 49152

// ---------------------------------------------------------------------------

extern "C" void kernel_launch(void* const* d_in, const int* in_sizes, int n_in,
                              void* d_out, int out_size) {
    (void)in_sizes; (void)n_in; (void)out_size;
    const float* x  = (const float*)d_in[0];
    const float* Wk = (const float*)d_in[1];
    const float* Wq = (const float*)d_in[2];
    const float* Wv = (const float*)d_in[3];
    const float* Wo = (const float*)d_in[4];
    const float* bo = (const float*)d_in[5];
    float* out = (float*)d_out;

    __half *xh, *wk, *wq, *wv, *wo, *gk, *gq, *gv, *ga;
    cudaGetSymbolAddress((void**)&xh, g_xh);
    cudaGetSymbolAddress((void**)&wk, g_wk);
    cudaGetSymbolAddress((void**)&wq, g_wq);
    cudaGetSymbolAddress((void**)&wv, g_wv);
    cudaGetSymbolAddress((void**)&wo, g_wo);
    cudaGetSymbolAddress((void**)&gk, g_k);
    cudaGetSymbolAddress((void**)&gq, g_q);
    cudaGetSymbolAddress((void**)&gv, g_v);
    cudaGetSymbolAddress((void**)&ga, g_att);

    cudaFuncSetAttribute(attn_h, cudaFuncAttributeMaxDynamicSharedMemorySize, ATTN_SMEM);
    cudaFuncSetAttribute(proj3, cudaFuncAttributeMaxDynamicSharedMemorySize, GEMM_SMEM);
    cudaFuncSetAttribute(gemm_out, cudaFuncAttributeMaxDynamicSharedMemorySize, GEMM_SMEM);

    cvt_x<<<Mn * En / 1024, 256>>>(x, xh);
    cvt_w<<<dim3(En * En / 1024, 4), 256>>>(Wk, Wq, Wv, Wo, wk, wq, wv, wo);

    dim3 gproj(Mn / 128, En / 128, 3);
    proj3<<<gproj, 256, GEMM_SMEM>>>(xh, wk, wq, wv, gk, gq, gv);

    dim3 gattn(Tn / 128, Hn, Bn);
    attn_h<<<gattn, 256, ATTN_SMEM>>>(gk, gq, gv, ga);

    dim3 gout(Mn / 128, En / 128);
    gemm_out<<<gout, 256, GEMM_SMEM>>>(ga, wo, bo, out);
}

// round 12
// speedup vs baseline: 11.0833x; 1.0070x over previous
#include <cuda_runtime.h>
#include <cuda_fp16.h>
#include <cstdint>
#include <math.h>

#define Bn 4
#define Tn 2048
#define En 1024
#define Hn 16
#define HSn 64
#define Mn (Bn * Tn)   // 8192

// Scratch buffers (device globals: allocation-free rule). fp16 everywhere.
__device__ __half g_xh[Mn * En];
__device__ __half g_wk[En * En];
__device__ __half g_wq[En * En];
__device__ __half g_wv[En * En];
__device__ __half g_wo[En * En];
__device__ __half g_k[Mn * En];
__device__ __half g_q[Mn * En];
__device__ __half g_v[Mn * En];
__device__ __half g_att[Mn * En];

__device__ __forceinline__ void mma_f16(float* c, const unsigned* a, const unsigned* b) {
    asm volatile(
        "mma.sync.aligned.m16n8k16.row.col.f32.f16.f16.f32 "
        "{%0,%1,%2,%3}, {%4,%5,%6,%7}, {%8,%9}, {%0,%1,%2,%3};"
        : "+f"(c[0]), "+f"(c[1]), "+f"(c[2]), "+f"(c[3])
        : "r"(a[0]), "r"(a[1]), "r"(a[2]), "r"(a[3]), "r"(b[0]), "r"(b[1]));
}
__device__ __forceinline__ void ldm_x4(unsigned* r, unsigned a) {
    asm volatile("ldmatrix.sync.aligned.m8n8.x4.shared.b16 {%0,%1,%2,%3}, [%4];"
                 : "=r"(r[0]), "=r"(r[1]), "=r"(r[2]), "=r"(r[3]) : "r"(a));
}
__device__ __forceinline__ void ldm_x4_t(unsigned* r, unsigned a) {
    asm volatile("ldmatrix.sync.aligned.m8n8.x4.trans.shared.b16 {%0,%1,%2,%3}, [%4];"
                 : "=r"(r[0]), "=r"(r[1]), "=r"(r[2]), "=r"(r[3]) : "r"(a));
}
__device__ __forceinline__ unsigned h2u(__half2 h) {
    return *reinterpret_cast<unsigned*>(&h);
}
__device__ __forceinline__ void cpa16(unsigned dst, const void* src) {
    asm volatile("cp.async.cg.shared.global [%0], [%1], 16;" :: "r"(dst), "l"(src));
}
__device__ __forceinline__ float ex2(float x) {   // raw MUFU.EX2, no pre-multiply
    float r;
    asm("ex2.approx.f32 %0, %1;" : "=f"(r) : "f"(x));
    return r;
}

// ---------------------------------------------------------------------------
// One-time fp32 -> fp16 conversion kernels
// ---------------------------------------------------------------------------
__global__ void cvt_x(const float* __restrict__ x, __half* __restrict__ xh) {
    size_t i = ((size_t)blockIdx.x * 256 + threadIdx.x) * 4;
    float4 v = *(const float4*)(x + i);
    *(uint2*)(xh + i) = make_uint2(h2u(__floats2half2_rn(v.x, v.y)),
                                   h2u(__floats2half2_rn(v.z, v.w)));
}
__global__ void cvt_w(const float* __restrict__ wk, const float* __restrict__ wq,
                      const float* __restrict__ wv, const float* __restrict__ wo,
                      __half* __restrict__ hk, __half* __restrict__ hq,
                      __half* __restrict__ hv, __half* __restrict__ ho) {
    const float* s;
    __half* d;
    float sc = 1.f;
    if (blockIdx.y == 0)      { s = wk; d = hk; sc = 0.125f * 1.4426950408889634f; }
    else if (blockIdx.y == 1) { s = wq; d = hq; }
    else if (blockIdx.y == 2) { s = wv; d = hv; }
    else                      { s = wo; d = ho; }
    size_t i = ((size_t)blockIdx.x * 256 + threadIdx.x) * 4;
    float4 v = *(const float4*)(s + i);
    *(uint2*)(d + i) = make_uint2(h2u(__floats2half2_rn(v.x * sc, v.y * sc)),
                                  h2u(__floats2half2_rn(v.z * sc, v.w * sc)));
}

// ===========================================================================
// FP16 NT GEMM body: C[M,N] = A[M,K] @ Bm[N,K]^T, 128x128 tile, BK=64,
// 3-stage cp.async ring, ONE __syncthreads per k-iter.
// smem row = 64 halves = 128B = 8 x 16B groups, swizzle phys = g ^ (row & 7).
// ===========================================================================
__device__ __forceinline__ void gemm_body(
    const __half* __restrict__ A, const __half* __restrict__ Bm,
    float acc[4][4][4], __half* sm, int m0, int n0) {
    const int tid = threadIdx.x, lane = tid & 31, warp = tid >> 5;
    const int wm = warp >> 2, wn = warp & 3;
    const int mq = lane >> 3, mr = lane & 7;
    const unsigned smb = (unsigned)__cvta_generic_to_shared(sm);

#define LOAD_STAGE(st, k0)                                                     \
    {                                                                          \
        _Pragma("unroll")                                                      \
        for (int i = 0; i < 4; i++) {                                          \
            int f = tid + i * 256;                                             \
            int r = f >> 3, g = f & 7;                                         \
            unsigned off = (unsigned)((r * 64 + ((g ^ (r & 7)) << 3)) * 2);    \
            cpa16(smb + (st) * 32768 + off,                                    \
                  A + (size_t)(m0 + r) * En + (k0) + g * 8);                   \
            cpa16(smb + (st) * 32768 + 16384 + off,                            \
                  Bm + (size_t)(n0 + r) * En + (k0) + g * 8);                  \
        }                                                                      \
        asm volatile("cp.async.commit_group;");                                \
    }

    LOAD_STAGE(0, 0)
    LOAD_STAGE(1, 64)
    for (int kt = 0; kt < 16; kt++) {
        if (kt < 15) asm volatile("cp.async.wait_group 1;");
        else         asm volatile("cp.async.wait_group 0;");
        __syncthreads();
        // Prefetch kt+2 into stage (kt+2)%3 == (kt-1)%3: all warps finished
        // reading it in iter kt-1, ordered by the sync we just passed.
        if (kt + 2 < 16) {
            int st = (kt + 2) % 3;
            LOAD_STAGE(st, (kt + 2) * 64)
        }

        const unsigned asb = smb + (kt % 3) * 32768;
        const unsigned bsb = asb + 16384;
#pragma unroll
        for (int kk = 0; kk < 4; kk++) {
            unsigned a[4][4], bfr[2][4];
#pragma unroll
            for (int mi = 0; mi < 4; mi++) {
                int row = wm * 64 + mi * 16 + (mq & 1) * 8 + mr;
                ldm_x4(a[mi], asb + row * 128 + (((2 * kk + (mq >> 1)) ^ mr) << 4));
            }
#pragma unroll
            for (int np = 0; np < 2; np++) {
                int row = wn * 32 + np * 16 + (mq >> 1) * 8 + mr;
                ldm_x4(bfr[np], bsb + row * 128 + (((2 * kk + (mq & 1)) ^ mr) << 4));
            }
#pragma unroll
            for (int mi = 0; mi < 4; mi++)
#pragma unroll
                for (int ni = 0; ni < 4; ni++)
                    mma_f16(acc[mi][ni], a[mi], &bfr[ni >> 1][(ni & 1) * 2]);
        }
    }
#undef LOAD_STAGE
}

static const int GEMM_SMEM = 3 * 32768;  // 98304

// ---------------------------------------------------------------------------
// Fused K/Q/V projection (z selects weight/output); fp16 in, fp16 out.
// ---------------------------------------------------------------------------
__global__ void __launch_bounds__(256, 2)
proj3(const __half* __restrict__ xh,
      const __half* __restrict__ wk, const __half* __restrict__ wq,
      const __half* __restrict__ wv,
      __half* __restrict__ gk, __half* __restrict__ gq, __half* __restrict__ gv) {
    extern __shared__ __align__(16) __half smg[];
    const __half* Bm;
    __half* C;
    if (blockIdx.z == 0)      { Bm = wk; C = gk; }
    else if (blockIdx.z == 1) { Bm = wq; C = gq; }
    else                      { Bm = wv; C = gv; }

    float acc[4][4][4];
#pragma unroll
    for (int mi = 0; mi < 4; mi++)
#pragma unroll
        for (int ni = 0; ni < 4; ni++)
#pragma unroll
            for (int r = 0; r < 4; r++) acc[mi][ni][r] = 0.f;

    const int m0 = blockIdx.x * 128, n0 = blockIdx.y * 128;
    gemm_body(xh, Bm, acc, smg, m0, n0);

    const int lane = threadIdx.x & 31, warp = threadIdx.x >> 5;
    const int wm = warp >> 2, wn = warp & 3;
    const int lr = lane >> 2, lc = lane & 3;
#pragma unroll
    for (int mi = 0; mi < 4; mi++) {
        int r = m0 + wm * 64 + mi * 16 + lr;
#pragma unroll
        for (int ni = 0; ni < 4; ni++) {
            int cb = n0 + wn * 32 + ni * 8 + 2 * lc;
            *(__half2*)(C + (size_t)r * En + cb) =
                __floats2half2_rn(acc[mi][ni][0], acc[mi][ni][1]);
            *(__half2*)(C + (size_t)(r + 8) * En + cb) =
                __floats2half2_rn(acc[mi][ni][2], acc[mi][ni][3]);
        }
    }
}

// ---------------------------------------------------------------------------
// Output projection: fp16 A x fp16 W^T + fp32 bias -> fp32 out
// ---------------------------------------------------------------------------
__global__ void __launch_bounds__(256, 2)
gemm_out(const __half* __restrict__ A, const __half* __restrict__ Bm,
         const float* __restrict__ bias, float* __restrict__ C) {
    extern __shared__ __align__(16) __half smg[];
    float acc[4][4][4];
#pragma unroll
    for (int mi = 0; mi < 4; mi++)
#pragma unroll
        for (int ni = 0; ni < 4; ni++)
#pragma unroll
            for (int r = 0; r < 4; r++) acc[mi][ni][r] = 0.f;

    const int m0 = blockIdx.x * 128, n0 = blockIdx.y * 128;
    gemm_body(A, Bm, acc, smg, m0, n0);

    const int lane = threadIdx.x & 31, warp = threadIdx.x >> 5;
    const int wm = warp >> 2, wn = warp & 3;
    const int lr = lane >> 2, lc = lane & 3;
#pragma unroll
    for (int mi = 0; mi < 4; mi++) {
        int r = m0 + wm * 64 + mi * 16 + lr;
#pragma unroll
        for (int ni = 0; ni < 4; ni++) {
            int cb = n0 + wn * 32 + ni * 8 + 2 * lc;
            float b0 = bias[cb], b1 = bias[cb + 1];
            C[(size_t)r * En + cb]           = acc[mi][ni][0] + b0;
            C[(size_t)r * En + cb + 1]       = acc[mi][ni][1] + b1;
            C[(size_t)(r + 8) * En + cb]     = acc[mi][ni][2] + b0;
            C[(size_t)(r + 8) * En + cb + 1] = acc[mi][ni][3] + b1;
        }
    }
}

// ---------------------------------------------------------------------------
// FP16 flash attention, register-direct P, Q frags hoisted, 3-stage KV ring
// with ONE __syncthreads per s-block. Scores in log2 domain (ex2 softmax).
// CTA: 128 t-rows x one (b,h). 8 warps x 16 rows. s tiled by 64, causal.
// smem: Qt 16KB | KV[3 stages][K 8KB | V 8KB] = 64KB.
// ---------------------------------------------------------------------------
__global__ void __launch_bounds__(256, 2)
attn_h(const __half* __restrict__ Kp, const __half* __restrict__ Qp,
       const __half* __restrict__ Vp, __half* __restrict__ Out) {
    extern __shared__ __align__(16) __half smh[];
    __half* Qt  = smh;              // [128][64]
    __half* KVs = Qt + 128 * 64;    // [3][K 64x64 | V 64x64]

    const int tid  = threadIdx.x;
    const int lane = tid & 31;
    const int warp = tid >> 5;
    const int lr   = lane >> 2;
    const int lc   = lane & 3;
    const int mq   = lane >> 3;
    const int mr   = lane & 7;

    const int tb = (gridDim.x - 1) - blockIdx.x;   // heavy tiles first
    const int h  = blockIdx.y;
    const int b  = blockIdx.z;
    const int t0 = tb * 128;

    const __half* kbase = Kp + (size_t)b * Tn * En + h * HSn;  // attention "Q"
    const __half* qbase = Qp + (size_t)b * Tn * En + h * HSn;  // attention "K"
    const __half* vbase = Vp + (size_t)b * Tn * En + h * HSn;

    const unsigned kvsmb = (unsigned)__cvta_generic_to_shared(KVs);

#define KV_PREFETCH(st, s0)                                                    \
    {                                                                          \
        _Pragma("unroll")                                                      \
        for (int i = 0; i < 2; i++) {                                          \
            int f = tid + i * 256;                                             \
            int r = f >> 3, g = f & 7;                                         \
            unsigned off = (unsigned)((r * 64 + ((g ^ (r & 7)) << 3)) * 2);    \
            cpa16(kvsmb + (st) * 16384 + off,                                  \
                  qbase + (size_t)((s0) + r) * En + g * 8);                    \
            cpa16(kvsmb + (st) * 16384 + 8192 + off,                           \
                  vbase + (size_t)((s0) + r) * En + g * 8);                    \
        }                                                                      \
        asm volatile("cp.async.commit_group;");                                \
    }

    const int nsb = 2 * tb + 2;   // >= 2 always
    KV_PREFETCH(0, 0)
    KV_PREFETCH(1, 64)

    // Load Q tile (pre-scaled fp16, log2 domain) with swizzle
#pragma unroll
    for (int i = 0; i < 4; i++) {
        int f = tid + i * 256;
        int r = f >> 3, g = f & 7;
        uint4 v = *(const uint4*)(kbase + (size_t)(t0 + r) * En + g * 8);
        *(uint4*)(Qt + r * 64 + ((g ^ (r & 7)) << 3)) = v;
    }
    __syncthreads();

    const unsigned qsmb = (unsigned)__cvta_generic_to_shared(Qt) +
                          (warp * 16 + (mq & 1) * 8 + mr) * 128;
    const int qsel = mq >> 1;
    const int ksel = mq & 1;
    const int vsel = mq >> 1;

    unsigned aq[4][4];          // Q fragments: invariant across s-blocks
#pragma unroll
    for (int kk = 0; kk < 4; kk++)
        ldm_x4(aq[kk], qsmb + (((2 * kk + qsel) ^ mr) << 4));

    float o[8][4];
#pragma unroll
    for (int ni = 0; ni < 8; ni++)
#pragma unroll
        for (int r = 0; r < 4; r++) o[ni][r] = 0.f;
    float m0f = -INFINITY, m1f = -INFINITY, l0 = 0.f, l1 = 0.f;

    const unsigned krowo = ((mq >> 1) * 8 + mr) * 128;       // within K stage
    const unsigned vrowo = 8192 + ((mq & 1) * 8 + mr) * 128; // within stage (V)

    const int row0 = t0 + warp * 16 + lr;
    const int row1 = row0 + 8;

    for (int sb = 0; sb < nsb; sb++) {
        const int s0 = sb * 64;
        if (sb < nsb - 1) asm volatile("cp.async.wait_group 1;");
        else              asm volatile("cp.async.wait_group 0;");
        __syncthreads();
        // Prefetch sb+2 into stage (sb+2)%3 == (sb-1)%3: all warps finished
        // reading it in iter sb-1, ordered by the sync above.
        if (sb + 2 < nsb) {
            int st = (sb + 2) % 3;
            KV_PREFETCH(st, (sb + 2) * 64)
        }

        const unsigned kst = kvsmb + (sb % 3) * 16384 + krowo;
        const unsigned vst = kvsmb + (sb % 3) * 16384 + vrowo;

        // ---- S = Q @ K^T  (log2 domain) ----
        float s[8][4];
#pragma unroll
        for (int ni = 0; ni < 8; ni++)
#pragma unroll
            for (int r = 0; r < 4; r++) s[ni][r] = 0.f;

#pragma unroll
        for (int kk = 0; kk < 4; kk++) {
#pragma unroll
            for (int np = 0; np < 4; np++) {
                unsigned kf[4];
                ldm_x4(kf, kst + np * 2048 + (((2 * kk + ksel) ^ mr) << 4));
                mma_f16(s[2 * np],     aq[kk], kf);
                mma_f16(s[2 * np + 1], aq[kk], kf + 2);
            }
        }

        // ---- causal mask (only diagonal-adjacent s-blocks) ----
        if (s0 + 63 > t0) {
#pragma unroll
            for (int ni = 0; ni < 8; ni++) {
                int c0 = s0 + ni * 8 + 2 * lc;
                if (c0 > row0)     s[ni][0] = -INFINITY;
                if (c0 + 1 > row0) s[ni][1] = -INFINITY;
                if (c0 > row1)     s[ni][2] = -INFINITY;
                if (c0 + 1 > row1) s[ni][3] = -INFINITY;
            }
        }

        // ---- online softmax, base-2 (rows within quad: shfl_xor 1,2) ----
        float rm0 = -INFINITY, rm1 = -INFINITY;
#pragma unroll
        for (int ni = 0; ni < 8; ni++) {
            rm0 = fmaxf(rm0, fmaxf(s[ni][0], s[ni][1]));
            rm1 = fmaxf(rm1, fmaxf(s[ni][2], s[ni][3]));
        }
        rm0 = fmaxf(rm0, __shfl_xor_sync(0xffffffffu, rm0, 1));
        rm0 = fmaxf(rm0, __shfl_xor_sync(0xffffffffu, rm0, 2));
        rm1 = fmaxf(rm1, __shfl_xor_sync(0xffffffffu, rm1, 1));
        rm1 = fmaxf(rm1, __shfl_xor_sync(0xffffffffu, rm1, 2));

        float mn0 = fmaxf(m0f, rm0);
        float mn1 = fmaxf(m1f, rm1);
        float corr0 = ex2(m0f - mn0);
        float corr1 = ex2(m1f - mn1);

        // P stays in registers: C-frag of S == A-frag of P (fp16 m16n8k16)
        unsigned ph[8][2];
        float rs0 = 0.f, rs1 = 0.f;
#pragma unroll
        for (int ni = 0; ni < 8; ni++) {
            float p0 = ex2(s[ni][0] - mn0);
            float p1 = ex2(s[ni][1] - mn0);
            float p2 = ex2(s[ni][2] - mn1);
            float p3 = ex2(s[ni][3] - mn1);
            rs0 += p0 + p1;
            rs1 += p2 + p3;
            ph[ni][0] = h2u(__floats2half2_rn(p0, p1));   // row lr
            ph[ni][1] = h2u(__floats2half2_rn(p2, p3));   // row lr+8
        }
        rs0 += __shfl_xor_sync(0xffffffffu, rs0, 1);
        rs0 += __shfl_xor_sync(0xffffffffu, rs0, 2);
        rs1 += __shfl_xor_sync(0xffffffffu, rs1, 1);
        rs1 += __shfl_xor_sync(0xffffffffu, rs1, 2);

        l0 = l0 * corr0 + rs0;
        l1 = l1 * corr1 + rs1;
        m0f = mn0;
        m1f = mn1;
#pragma unroll
        for (int ni = 0; ni < 8; ni++) {
            o[ni][0] *= corr0;
            o[ni][1] *= corr0;
            o[ni][2] *= corr1;
            o[ni][3] *= corr1;
        }

        // ---- O += P @ V (A-frags straight from registers) ----
#pragma unroll
        for (int kk = 0; kk < 4; kk++) {
            unsigned ap[4] = { ph[2 * kk][0], ph[2 * kk][1],
                               ph[2 * kk + 1][0], ph[2 * kk + 1][1] };
#pragma unroll
            for (int np = 0; np < 4; np++) {
                unsigned vf[4];
                ldm_x4_t(vf, vst + kk * 2048 + (((2 * np + vsel) ^ mr) << 4));
                mma_f16(o[2 * np],     ap, vf);
                mma_f16(o[2 * np + 1], ap, vf + 2);
            }
        }
    }
#undef KV_PREFETCH

    // ---- epilogue: normalize, fp16 store ----
    float inv0 = 1.f / l0;
    float inv1 = 1.f / l1;
    __half* ob = Out + (size_t)b * Tn * En + h * HSn;
#pragma unroll
    for (int ni = 0; ni < 8; ni++) {
        int c = ni * 8 + 2 * lc;
        *(__half2*)(ob + (size_t)row0 * En + c) =
            __floats2half2_rn(o[ni][0] * inv0, o[ni][1] * inv0);
        *(__half2*)(ob + (size_t)row1 * En + c) =
            __floats2half2_rn(o[ni][2] * inv1, o[ni][3] * inv1);
    }
}

static const int ATTN_SMEM = (128 * 64 + 3 * 2 * 64 * 64) * 2;  // 65536

// ---------------------------------------------------------------------------

extern "C" void kernel_launch(void* const* d_in, const int* in_sizes, int n_in,
                              void* d_out, int out_size) {
    (void)in_sizes; (void)n_in; (void)out_size;
    const float* x  = (const float*)d_in[0];
    const float* Wk = (const float*)d_in[1];
    const float* Wq = (const float*)d_in[2];
    const float* Wv = (const float*)d_in[3];
    const float* Wo = (const float*)d_in[4];
    const float* bo = (const float*)d_in[5];
    float* out = (float*)d_out;

    __half *xh, *wk, *wq, *wv, *wo, *gk, *gq, *gv, *ga;
    cudaGetSymbolAddress((void**)&xh, g_xh);
    cudaGetSymbolAddress((void**)&wk, g_wk);
    cudaGetSymbolAddress((void**)&wq, g_wq);
    cudaGetSymbolAddress((void**)&wv, g_wv);
    cudaGetSymbolAddress((void**)&wo, g_wo);
    cudaGetSymbolAddress((void**)&gk, g_k);
    cudaGetSymbolAddress((void**)&gq, g_q);
    cudaGetSymbolAddress((void**)&gv, g_v);
    cudaGetSymbolAddress((void**)&ga, g_att);

    cudaFuncSetAttribute(attn_h, cudaFuncAttributeMaxDynamicSharedMemorySize, ATTN_SMEM);
    cudaFuncSetAttribute(proj3, cudaFuncAttributeMaxDynamicSharedMemorySize, GEMM_SMEM);
    cudaFuncSetAttribute(gemm_out, cudaFuncAttributeMaxDynamicSharedMemorySize, GEMM_SMEM);

    cvt_x<<<Mn * En / 1024, 256>>>(x, xh);
    cvt_w<<<dim3(En * En / 1024, 4), 256>>>(Wk, Wq, Wv, Wo, wk, wq, wv, wo);

    dim3 gproj(Mn / 128, En / 128, 3);
    proj3<<<gproj, 256, GEMM_SMEM>>>(xh, wk, wq, wv, gk, gq, gv);

    dim3 gattn(Tn / 128, Hn, Bn);
    attn_h<<<gattn, 256, ATTN_SMEM>>>(gk, gq, gv, ga);

    dim3 gout(Mn / 128, En / 128);
    gemm_out<<<gout, 256, GEMM_SMEM>>>(ga, wo, bo, out);
}

// round 14
// speedup vs baseline: 11.6673x; 1.0527x over previous
#include <cuda_runtime.h>
#include <cuda_fp16.h>
#include <cstdint>
#include <math.h>

#define Bn 4
#define Tn 2048
#define En 1024
#define Hn 16
#define HSn 64
#define Mn (Bn * Tn)   // 8192

// Scratch buffers (device globals: allocation-free rule). fp16 everywhere.
__device__ __half g_xh[Mn * En];
__device__ __half g_wk[En * En];
__device__ __half g_wq[En * En];
__device__ __half g_wv[En * En];
__device__ __half g_wo[En * En];
__device__ __half g_k[Mn * En];
__device__ __half g_q[Mn * En];
__device__ __half g_v[Mn * En];
__device__ __half g_att[Mn * En];

__device__ __forceinline__ void mma_f16(float* c, const unsigned* a, const unsigned* b) {
    asm volatile(
        "mma.sync.aligned.m16n8k16.row.col.f32.f16.f16.f32 "
        "{%0,%1,%2,%3}, {%4,%5,%6,%7}, {%8,%9}, {%0,%1,%2,%3};"
        : "+f"(c[0]), "+f"(c[1]), "+f"(c[2]), "+f"(c[3])
        : "r"(a[0]), "r"(a[1]), "r"(a[2]), "r"(a[3]), "r"(b[0]), "r"(b[1]));
}
__device__ __forceinline__ void ldm_x4(unsigned* r, unsigned a) {
    asm volatile("ldmatrix.sync.aligned.m8n8.x4.shared.b16 {%0,%1,%2,%3}, [%4];"
                 : "=r"(r[0]), "=r"(r[1]), "=r"(r[2]), "=r"(r[3]) : "r"(a));
}
__device__ __forceinline__ void ldm_x4_t(unsigned* r, unsigned a) {
    asm volatile("ldmatrix.sync.aligned.m8n8.x4.trans.shared.b16 {%0,%1,%2,%3}, [%4];"
                 : "=r"(r[0]), "=r"(r[1]), "=r"(r[2]), "=r"(r[3]) : "r"(a));
}
__device__ __forceinline__ unsigned h2u(__half2 h) {
    return *reinterpret_cast<unsigned*>(&h);
}
__device__ __forceinline__ void cpa16(unsigned dst, const void* src) {
    asm volatile("cp.async.cg.shared.global [%0], [%1], 16;" :: "r"(dst), "l"(src));
}
__device__ __forceinline__ float ex2(float x) {   // raw MUFU.EX2 (fp32)
    float r;
    asm("ex2.approx.f32 %0, %1;" : "=f"(r) : "f"(x));
    return r;
}
__device__ __forceinline__ unsigned ex2h2(unsigned x) {  // packed fp16x2 exp2
    unsigned r;
    asm("ex2.approx.f16x2 %0, %1;" : "=r"(r) : "r"(x));
    return r;
}

// ---------------------------------------------------------------------------
// One-time fp32 -> fp16 conversion (single fused launch).
// blocks: [0,8192) x | [8192,9216) Wk*0.125*log2e | then Wq | Wv | Wo
// ---------------------------------------------------------------------------
__global__ void cvt_all(const float* __restrict__ x,
                        const float* __restrict__ wk, const float* __restrict__ wq,
                        const float* __restrict__ wv, const float* __restrict__ wo,
                        __half* __restrict__ xh,
                        __half* __restrict__ hk, __half* __restrict__ hq,
                        __half* __restrict__ hv, __half* __restrict__ ho) {
    int bid = blockIdx.x;
    const float* s;
    __half* d;
    float sc = 1.f;
    size_t base;
    if (bid < 8192)       { s = x;  d = xh; base = (size_t)bid * 1024; }
    else if (bid < 9216)  { s = wk; d = hk; base = (size_t)(bid - 8192) * 1024;
                            sc = 0.125f * 1.4426950408889634f; }
    else if (bid < 10240) { s = wq; d = hq; base = (size_t)(bid - 9216) * 1024; }
    else if (bid < 11264) { s = wv; d = hv; base = (size_t)(bid - 10240) * 1024; }
    else                  { s = wo; d = ho; base = (size_t)(bid - 11264) * 1024; }
    size_t i = base + (size_t)threadIdx.x * 4;
    float4 v = *(const float4*)(s + i);
    *(uint2*)(d + i) = make_uint2(h2u(__floats2half2_rn(v.x * sc, v.y * sc)),
                                  h2u(__floats2half2_rn(v.z * sc, v.w * sc)));
}

// ===========================================================================
// FP16 NT GEMM body: C[M,N] = A[M,K] @ Bm[N,K]^T, 128x128 tile, BK=64,
// 3-stage cp.async ring, ONE __syncthreads per k-iter. (R12 config.)
// ===========================================================================
__device__ __forceinline__ void gemm_body(
    const __half* __restrict__ A, const __half* __restrict__ Bm,
    float acc[4][4][4], __half* sm, int m0, int n0) {
    const int tid = threadIdx.x, lane = tid & 31, warp = tid >> 5;
    const int wm = warp >> 2, wn = warp & 3;
    const int mq = lane >> 3, mr = lane & 7;
    const unsigned smb = (unsigned)__cvta_generic_to_shared(sm);

#define LOAD_STAGE(st, k0)                                                     \
    {                                                                          \
        _Pragma("unroll")                                                      \
        for (int i = 0; i < 4; i++) {                                          \
            int f = tid + i * 256;                                             \
            int r = f >> 3, g = f & 7;                                         \
            unsigned off = (unsigned)((r * 64 + ((g ^ (r & 7)) << 3)) * 2);    \
            cpa16(smb + (st) * 32768 + off,                                    \
                  A + (size_t)(m0 + r) * En + (k0) + g * 8);                   \
            cpa16(smb + (st) * 32768 + 16384 + off,                            \
                  Bm + (size_t)(n0 + r) * En + (k0) + g * 8);                  \
        }                                                                      \
        asm volatile("cp.async.commit_group;");                                \
    }

    LOAD_STAGE(0, 0)
    LOAD_STAGE(1, 64)
    for (int kt = 0; kt < 16; kt++) {
        if (kt < 15) asm volatile("cp.async.wait_group 1;");
        else         asm volatile("cp.async.wait_group 0;");
        __syncthreads();
        if (kt + 2 < 16) {
            int st = (kt + 2) % 3;
            LOAD_STAGE(st, (kt + 2) * 64)
        }

        const unsigned asb = smb + (kt % 3) * 32768;
        const unsigned bsb = asb + 16384;
#pragma unroll
        for (int kk = 0; kk < 4; kk++) {
            unsigned a[4][4], bfr[2][4];
#pragma unroll
            for (int mi = 0; mi < 4; mi++) {
                int row = wm * 64 + mi * 16 + (mq & 1) * 8 + mr;
                ldm_x4(a[mi], asb + row * 128 + (((2 * kk + (mq >> 1)) ^ mr) << 4));
            }
#pragma unroll
            for (int np = 0; np < 2; np++) {
                int row = wn * 32 + np * 16 + (mq >> 1) * 8 + mr;
                ldm_x4(bfr[np], bsb + row * 128 + (((2 * kk + (mq & 1)) ^ mr) << 4));
            }
#pragma unroll
            for (int mi = 0; mi < 4; mi++)
#pragma unroll
                for (int ni = 0; ni < 4; ni++)
                    mma_f16(acc[mi][ni], a[mi], &bfr[ni >> 1][(ni & 1) * 2]);
        }
    }
#undef LOAD_STAGE
}

static const int GEMM_SMEM = 3 * 32768;  // 98304

// ---------------------------------------------------------------------------
// Fused K/Q/V projection (z selects weight/output); fp16 in, fp16 out.
// ---------------------------------------------------------------------------
__global__ void __launch_bounds__(256, 2)
proj3(const __half* __restrict__ xh,
      const __half* __restrict__ wk, const __half* __restrict__ wq,
      const __half* __restrict__ wv,
      __half* __restrict__ gk, __half* __restrict__ gq, __half* __restrict__ gv) {
    extern __shared__ __align__(16) __half smg[];
    const __half* Bm;
    __half* C;
    if (blockIdx.z == 0)      { Bm = wk; C = gk; }
    else if (blockIdx.z == 1) { Bm = wq; C = gq; }
    else                      { Bm = wv; C = gv; }

    float acc[4][4][4];
#pragma unroll
    for (int mi = 0; mi < 4; mi++)
#pragma unroll
        for (int ni = 0; ni < 4; ni++)
#pragma unroll
            for (int r = 0; r < 4; r++) acc[mi][ni][r] = 0.f;

    const int m0 = blockIdx.x * 128, n0 = blockIdx.y * 128;
    gemm_body(xh, Bm, acc, smg, m0, n0);

    const int lane = threadIdx.x & 31, warp = threadIdx.x >> 5;
    const int wm = warp >> 2, wn = warp & 3;
    const int lr = lane >> 2, lc = lane & 3;
#pragma unroll
    for (int mi = 0; mi < 4; mi++) {
        int r = m0 + wm * 64 + mi * 16 + lr;
#pragma unroll
        for (int ni = 0; ni < 4; ni++) {
            int cb = n0 + wn * 32 + ni * 8 + 2 * lc;
            *(__half2*)(C + (size_t)r * En + cb) =
                __floats2half2_rn(acc[mi][ni][0], acc[mi][ni][1]);
            *(__half2*)(C + (size_t)(r + 8) * En + cb) =
                __floats2half2_rn(acc[mi][ni][2], acc[mi][ni][3]);
        }
    }
}

// ---------------------------------------------------------------------------
// Output projection: fp16 A x fp16 W^T + fp32 bias -> fp32 out
// ---------------------------------------------------------------------------
__global__ void __launch_bounds__(256, 2)
gemm_out(const __half* __restrict__ A, const __half* __restrict__ Bm,
         const float* __restrict__ bias, float* __restrict__ C) {
    extern __shared__ __align__(16) __half smg[];
    float acc[4][4][4];
#pragma unroll
    for (int mi = 0; mi < 4; mi++)
#pragma unroll
        for (int ni = 0; ni < 4; ni++)
#pragma unroll
            for (int r = 0; r < 4; r++) acc[mi][ni][r] = 0.f;

    const int m0 = blockIdx.x * 128, n0 = blockIdx.y * 128;
    gemm_body(A, Bm, acc, smg, m0, n0);

    const int lane = threadIdx.x & 31, warp = threadIdx.x >> 5;
    const int wm = warp >> 2, wn = warp & 3;
    const int lr = lane >> 2, lc = lane & 3;
#pragma unroll
    for (int mi = 0; mi < 4; mi++) {
        int r = m0 + wm * 64 + mi * 16 + lr;
#pragma unroll
        for (int ni = 0; ni < 4; ni++) {
            int cb = n0 + wn * 32 + ni * 8 + 2 * lc;
            float b0 = bias[cb], b1 = bias[cb + 1];
            C[(size_t)r * En + cb]           = acc[mi][ni][0] + b0;
            C[(size_t)r * En + cb + 1]       = acc[mi][ni][1] + b1;
            C[(size_t)(r + 8) * En + cb]     = acc[mi][ni][2] + b0;
            C[(size_t)(r + 8) * En + cb + 1] = acc[mi][ni][3] + b1;
        }
    }
}

// ---------------------------------------------------------------------------
// FP16 flash attention: register-direct P, fp16x2 exp2 softmax, row-sum via
// constant ones-column MMA (l accumulated alongside O, corrected uniformly).
// 3-stage KV ring, ONE __syncthreads per s-block. s tiled by 64, causal.
// smem: Qt 16KB | KV[3 stages][K 8KB | V 8KB] = 64KB.
// ---------------------------------------------------------------------------
__global__ void __launch_bounds__(256, 2)
attn_h(const __half* __restrict__ Kp, const __half* __restrict__ Qp,
       const __half* __restrict__ Vp, __half* __restrict__ Out) {
    extern __shared__ __align__(16) __half smh[];
    __half* Qt  = smh;              // [128][64]
    __half* KVs = Qt + 128 * 64;    // [3][K 64x64 | V 64x64]

    const int tid  = threadIdx.x;
    const int lane = tid & 31;
    const int warp = tid >> 5;
    const int lr   = lane >> 2;
    const int lc   = lane & 3;
    const int mq   = lane >> 3;
    const int mr   = lane & 7;

    const int tb = (gridDim.x - 1) - blockIdx.x;   // heavy tiles first
    const int h  = blockIdx.y;
    const int b  = blockIdx.z;
    const int t0 = tb * 128;

    const __half* kbase = Kp + (size_t)b * Tn * En + h * HSn;  // attention "Q"
    const __half* qbase = Qp + (size_t)b * Tn * En + h * HSn;  // attention "K"
    const __half* vbase = Vp + (size_t)b * Tn * En + h * HSn;

    const unsigned kvsmb = (unsigned)__cvta_generic_to_shared(KVs);

#define KV_PREFETCH(st, s0)                                                    \
    {                                                                          \
        _Pragma("unroll")                                                      \
        for (int i = 0; i < 2; i++) {                                          \
            int f = tid + i * 256;                                             \
            int r = f >> 3, g = f & 7;                                         \
            unsigned off = (unsigned)((r * 64 + ((g ^ (r & 7)) << 3)) * 2);    \
            cpa16(kvsmb + (st) * 16384 + off,                                  \
                  qbase + (size_t)((s0) + r) * En + g * 8);                    \
            cpa16(kvsmb + (st) * 16384 + 8192 + off,                           \
                  vbase + (size_t)((s0) + r) * En + g * 8);                    \
        }                                                                      \
        asm volatile("cp.async.commit_group;");                                \
    }

    const int nsb = 2 * tb + 2;   // >= 2 always
    KV_PREFETCH(0, 0)
    KV_PREFETCH(1, 64)

    // Load Q tile (pre-scaled fp16, log2 domain) with swizzle
#pragma unroll
    for (int i = 0; i < 4; i++) {
        int f = tid + i * 256;
        int r = f >> 3, g = f & 7;
        uint4 v = *(const uint4*)(kbase + (size_t)(t0 + r) * En + g * 8);
        *(uint4*)(Qt + r * 64 + ((g ^ (r & 7)) << 3)) = v;
    }
    __syncthreads();

    const unsigned qsmb = (unsigned)__cvta_generic_to_shared(Qt) +
                          (warp * 16 + (mq & 1) * 8 + mr) * 128;
    const int qsel = mq >> 1;
    const int ksel = mq & 1;
    const int vsel = mq >> 1;

    unsigned aq[4][4];          // Q fragments: invariant across s-blocks
#pragma unroll
    for (int kk = 0; kk < 4; kk++)
        ldm_x4(aq[kk], qsmb + (((2 * kk + qsel) ^ mr) << 4));

    float o[8][4];
#pragma unroll
    for (int ni = 0; ni < 8; ni++)
#pragma unroll
        for (int r = 0; r < 4; r++) o[ni][r] = 0.f;
    float ol[4] = {0.f, 0.f, 0.f, 0.f};   // ones-column accumulator: l in col 64
    float m0f = -INFINITY, m1f = -INFINITY;

    // Constant B-frag for the ones column: B[k][64+n]=1 iff n==0 (lanes lr==0)
    const unsigned onesw = (lr == 0) ? 0x3C003C00u : 0u;
    const unsigned onesfrag[2] = { onesw, onesw };

    const unsigned krowo = ((mq >> 1) * 8 + mr) * 128;       // within K stage
    const unsigned vrowo = 8192 + ((mq & 1) * 8 + mr) * 128; // within stage (V)

    const int row0 = t0 + warp * 16 + lr;
    const int row1 = row0 + 8;

    for (int sb = 0; sb < nsb; sb++) {
        const int s0 = sb * 64;
        if (sb < nsb - 1) asm volatile("cp.async.wait_group 1;");
        else              asm volatile("cp.async.wait_group 0;");
        __syncthreads();
        if (sb + 2 < nsb) {
            int st = (sb + 2) % 3;
            KV_PREFETCH(st, (sb + 2) * 64)
        }

        const unsigned kst = kvsmb + (sb % 3) * 16384 + krowo;
        const unsigned vst = kvsmb + (sb % 3) * 16384 + vrowo;

        // ---- S = Q @ K^T  (log2 domain) ----
        float s[8][4];
#pragma unroll
        for (int ni = 0; ni < 8; ni++)
#pragma unroll
            for (int r = 0; r < 4; r++) s[ni][r] = 0.f;

#pragma unroll
        for (int kk = 0; kk < 4; kk++) {
#pragma unroll
            for (int np = 0; np < 4; np++) {
                unsigned kf[4];
                ldm_x4(kf, kst + np * 2048 + (((2 * kk + ksel) ^ mr) << 4));
                mma_f16(s[2 * np],     aq[kk], kf);
                mma_f16(s[2 * np + 1], aq[kk], kf + 2);
            }
        }

        // ---- causal mask (only diagonal-adjacent s-blocks) ----
        if (s0 + 63 > t0) {
#pragma unroll
            for (int ni = 0; ni < 8; ni++) {
                int c0 = s0 + ni * 8 + 2 * lc;
                if (c0 > row0)     s[ni][0] = -INFINITY;
                if (c0 + 1 > row0) s[ni][1] = -INFINITY;
                if (c0 > row1)     s[ni][2] = -INFINITY;
                if (c0 + 1 > row1) s[ni][3] = -INFINITY;
            }
        }

        // ---- online softmax, base-2 (rows within quad: shfl_xor 1,2) ----
        float rm0 = -INFINITY, rm1 = -INFINITY;
#pragma unroll
        for (int ni = 0; ni < 8; ni++) {
            rm0 = fmaxf(rm0, fmaxf(s[ni][0], s[ni][1]));
            rm1 = fmaxf(rm1, fmaxf(s[ni][2], s[ni][3]));
        }
        rm0 = fmaxf(rm0, __shfl_xor_sync(0xffffffffu, rm0, 1));
        rm0 = fmaxf(rm0, __shfl_xor_sync(0xffffffffu, rm0, 2));
        rm1 = fmaxf(rm1, __shfl_xor_sync(0xffffffffu, rm1, 1));
        rm1 = fmaxf(rm1, __shfl_xor_sync(0xffffffffu, rm1, 2));

        float mn0 = fmaxf(m0f, rm0);
        float mn1 = fmaxf(m1f, rm1);
        float corr0 = ex2(m0f - mn0);
        float corr1 = ex2(m1f - mn1);
        m0f = mn0;
        m1f = mn1;

        // P in registers via packed fp16x2 exp2 (C-frag of S == A-frag of P)
        unsigned ph[8][2];
#pragma unroll
        for (int ni = 0; ni < 8; ni++) {
            ph[ni][0] = ex2h2(h2u(__floats2half2_rn(s[ni][0] - mn0, s[ni][1] - mn0)));
            ph[ni][1] = ex2h2(h2u(__floats2half2_rn(s[ni][2] - mn1, s[ni][3] - mn1)));
        }

#pragma unroll
        for (int ni = 0; ni < 8; ni++) {
            o[ni][0] *= corr0;
            o[ni][1] *= corr0;
            o[ni][2] *= corr1;
            o[ni][3] *= corr1;
        }
        ol[0] *= corr0;
        ol[2] *= corr1;

        // ---- O += P @ V; l accumulates via constant ones-frag MMA ----
#pragma unroll
        for (int kk = 0; kk < 4; kk++) {
            unsigned ap[4] = { ph[2 * kk][0], ph[2 * kk][1],
                               ph[2 * kk + 1][0], ph[2 * kk + 1][1] };
#pragma unroll
            for (int np = 0; np < 4; np++) {
                unsigned vf[4];
                ldm_x4_t(vf, vst + kk * 2048 + (((2 * np + vsel) ^ mr) << 4));
                mma_f16(o[2 * np],     ap, vf);
                mma_f16(o[2 * np + 1], ap, vf + 2);
            }
            mma_f16(ol, ap, onesfrag);
        }
    }
#undef KV_PREFETCH

    // ---- epilogue: extract l (col 64, lanes lc==0), normalize, store ----
    float l0 = __shfl_sync(0xffffffffu, ol[0], lane & ~3);
    float l1 = __shfl_sync(0xffffffffu, ol[2], lane & ~3);
    float inv0 = 1.f / l0;
    float inv1 = 1.f / l1;
    __half* ob = Out + (size_t)b * Tn * En + h * HSn;
#pragma unroll
    for (int ni = 0; ni < 8; ni++) {
        int c = ni * 8 + 2 * lc;
        *(__half2*)(ob + (size_t)row0 * En + c) =
            __floats2half2_rn(o[ni][0] * inv0, o[ni][1] * inv0);
        *(__half2*)(ob + (size_t)row1 * En + c) =
            __floats2half2_rn(o[ni][2] * inv1, o[ni][3] * inv1);
    }
}

static const int ATTN_SMEM = (128 * 64 + 3 * 2 * 64 * 64) * 2;  // 65536

// ---------------------------------------------------------------------------

extern "C" void kernel_launch(void* const* d_in, const int* in_sizes, int n_in,
                              void* d_out, int out_size) {
    (void)in_sizes; (void)n_in; (void)out_size;
    const float* x  = (const float*)d_in[0];
    const float* Wk = (const float*)d_in[1];
    const float* Wq = (const float*)d_in[2];
    const float* Wv = (const float*)d_in[3];
    const float* Wo = (const float*)d_in[4];
    const float* bo = (const float*)d_in[5];
    float* out = (float*)d_out;

    __half *xh, *wk, *wq, *wv, *wo, *gk, *gq, *gv, *ga;
    cudaGetSymbolAddress((void**)&xh, g_xh);
    cudaGetSymbolAddress((void**)&wk, g_wk);
    cudaGetSymbolAddress((void**)&wq, g_wq);
    cudaGetSymbolAddress((void**)&wv, g_wv);
    cudaGetSymbolAddress((void**)&wo, g_wo);
    cudaGetSymbolAddress((void**)&gk, g_k);
    cudaGetSymbolAddress((void**)&gq, g_q);
    cudaGetSymbolAddress((void**)&gv, g_v);
    cudaGetSymbolAddress((void**)&ga, g_att);

    cudaFuncSetAttribute(attn_h, cudaFuncAttributeMaxDynamicSharedMemorySize, ATTN_SMEM);
    cudaFuncSetAttribute(proj3, cudaFuncAttributeMaxDynamicSharedMemorySize, GEMM_SMEM);
    cudaFuncSetAttribute(gemm_out, cudaFuncAttributeMaxDynamicSharedMemorySize, GEMM_SMEM);

    cvt_all<<<12288, 256>>>(x, Wk, Wq, Wv, Wo, xh, wk, wq, wv, wo);

    dim3 gproj(Mn / 128, En / 128, 3);
    proj3<<<gproj, 256, GEMM_SMEM>>>(xh, wk, wq, wv, gk, gq, gv);

    dim3 gattn(Tn / 128, Hn, Bn);
    attn_h<<<gattn, 256, ATTN_SMEM>>>(gk, gq, gv, ga);

    dim3 gout(Mn / 128, En / 128);
    gemm_out<<<gout, 256, GEMM_SMEM>>>(ga, wo, bo, out);
}